// round 1
// baseline (speedup 1.0000x reference)
#include <cuda_runtime.h>
#include <math.h>
#include <stdint.h>

// ---------------------------------------------------------------------------
// Problem constants
// ---------------------------------------------------------------------------
#define NB    4
#define CDIM  128
#define HWP   4096           // 64*64
#define ROWS  (NB * HWP)     // 16384
#define NHEAD 4
#define DH    32
#define KS    7

// Scratch arena layout (floats)
#define OFF_XS    0u
#define OFF_XN    2097152u            // 16384*128
#define OFF_QKV   4194304u            // len 16384*384
#define OFF_T1    10485760u           // len 16384*32
#define OFF_T     11010048u           // len 16384*128
#define OFF_NA    13107200u
#define OFF_X2    15204352u
#define OFF_XN2   17301504u
#define OFF_H1    19398656u           // len 16384*512
#define OFF_GSUM  27787264u           // 512
#define OFF_G     27787776u           // 512
#define SCRATCH_FLOATS 27788288u

__device__ float d_scratch[SCRATCH_FLOATS];

__device__ __forceinline__ float gelu_exact(float x) {
    return 0.5f * x * (1.0f + erff(x * 0.7071067811865476f));
}

// ---------------------------------------------------------------------------
// Kernel 1: NCHW -> NHWC transpose + LayerNorm1.  32 pixels per block.
// ---------------------------------------------------------------------------
__global__ __launch_bounds__(128)
void k_transpose_ln(const float* __restrict__ x,
                    const float* __restrict__ w, const float* __restrict__ b,
                    float* __restrict__ xs, float* __restrict__ xn)
{
    __shared__ float s[32][129];
    __shared__ float smu[32], srs[32];
    int tid = threadIdx.x;
    int row0 = blockIdx.x * 32;
    int n  = row0 >> 12;
    int p0 = row0 & 4095;
    int pl = tid & 31;
    int cg = tid >> 5;       // 0..3

    #pragma unroll 4
    for (int it = 0; it < 32; it++) {
        int c = it * 4 + cg;
        s[pl][c] = x[((size_t)(n * CDIM + c) << 12) + p0 + pl];
    }
    __syncthreads();

    if (tid < 32) {
        float sum = 0.f, sq = 0.f;
        #pragma unroll 8
        for (int c = 0; c < CDIM; c++) { float v = s[tid][c]; sum += v; sq += v * v; }
        float mu  = sum * (1.0f / CDIM);
        float var = sq * (1.0f / CDIM) - mu * mu;
        smu[tid] = mu;
        srs[tid] = rsqrtf(var + 1e-5f);
    }
    __syncthreads();

    float wc = w[tid], bc = b[tid];
    #pragma unroll 4
    for (int it = 0; it < 32; it++) {
        float v = s[it][tid];
        size_t o = (size_t)(row0 + it) * CDIM + tid;
        xs[o] = v;
        xn[o] = (v - smu[it]) * srs[it] * wc + bc;
    }
}

// ---------------------------------------------------------------------------
// Generic tiled fp32 GEMM: C[M,N] = A[M,K] @ B[K,N] + bias, with epilogues.
// BM=128, BN=64, BK=16, 256 threads, 8x4 per thread.
// ---------------------------------------------------------------------------
#define EPI_NONE 0
#define EPI_GELU 1
#define EPI_X2   2   // x2 = acc+bias + e1(xs) + e2(t)*e3(g[batch])*0.02
#define EPI_OUT  3   // out NCHW = acc+bias + e1(x2)

template<int EPI>
__global__ __launch_bounds__(256)
void k_gemm(const float* __restrict__ A, const float* __restrict__ B,
            const float* __restrict__ bias, float* __restrict__ C,
            int M, int N, int K,
            const float* __restrict__ e1, const float* __restrict__ e2,
            const float* __restrict__ e3)
{
    __shared__ float As[16][128];
    __shared__ float Bs[16][64];

    int tid = threadIdx.x;
    int m0 = blockIdx.y * 128;
    int n0 = blockIdx.x * 64;
    int tx = tid & 15;       // col group: cols tx*4..+3
    int ty = tid >> 4;       // row group: rows ty*8..+7
    int arow  = tid >> 1;
    int akoff = (tid & 1) * 8;
    int brow  = tid >> 4;
    int bcol  = (tid & 15) * 4;

    float acc[8][4];
    #pragma unroll
    for (int i = 0; i < 8; i++)
        #pragma unroll
        for (int j = 0; j < 4; j++) acc[i][j] = 0.f;

    for (int k0 = 0; k0 < K; k0 += 16) {
        const float* Ap = A + (size_t)(m0 + arow) * K + k0 + akoff;
        float4 a0 = *(const float4*)Ap;
        float4 a1 = *(const float4*)(Ap + 4);
        As[akoff + 0][arow] = a0.x; As[akoff + 1][arow] = a0.y;
        As[akoff + 2][arow] = a0.z; As[akoff + 3][arow] = a0.w;
        As[akoff + 4][arow] = a1.x; As[akoff + 5][arow] = a1.y;
        As[akoff + 6][arow] = a1.z; As[akoff + 7][arow] = a1.w;

        float4 b4 = make_float4(0.f, 0.f, 0.f, 0.f);
        if (n0 + bcol < N)
            b4 = *(const float4*)(B + (size_t)(k0 + brow) * N + n0 + bcol);
        *(float4*)&Bs[brow][bcol] = b4;
        __syncthreads();

        #pragma unroll
        for (int kk = 0; kk < 16; kk++) {
            float a[8], bb[4];
            #pragma unroll
            for (int i = 0; i < 8; i++) a[i] = As[kk][ty * 8 + i];
            #pragma unroll
            for (int j = 0; j < 4; j++) bb[j] = Bs[kk][tx * 4 + j];
            #pragma unroll
            for (int i = 0; i < 8; i++)
                #pragma unroll
                for (int j = 0; j < 4; j++)
                    acc[i][j] = fmaf(a[i], bb[j], acc[i][j]);
        }
        __syncthreads();
    }

    #pragma unroll
    for (int i = 0; i < 8; i++) {
        int row = m0 + ty * 8 + i;
        #pragma unroll
        for (int j = 0; j < 4; j++) {
            int col = n0 + tx * 4 + j;
            if (col >= N) continue;
            float v = acc[i][j] + bias[col];
            if (EPI == EPI_GELU) {
                C[(size_t)row * N + col] = gelu_exact(v);
            } else if (EPI == EPI_NONE) {
                C[(size_t)row * N + col] = v;
            } else if (EPI == EPI_X2) {
                int bn = row >> 12;
                v += e1[(size_t)row * CDIM + col]
                   + e2[(size_t)row * CDIM + col] * e3[bn * CDIM + col] * 0.02f;
                C[(size_t)row * CDIM + col] = v;
            } else { // EPI_OUT: write NCHW
                v += e1[(size_t)row * CDIM + col];
                int bn = row >> 12, p = row & 4095;
                C[((size_t)(bn * CDIM + col) << 12) + p] = v;
            }
        }
    }
}

// ---------------------------------------------------------------------------
// Channel-attention reductions
// ---------------------------------------------------------------------------
__global__ void k_zero(float* __restrict__ gsum) {
    gsum[threadIdx.x] = 0.f;   // 512 threads
}

__global__ __launch_bounds__(128)
void k_gmean(const float* __restrict__ t, float* __restrict__ gsum)
{
    int n = blockIdx.x, chunk = blockIdx.y;
    int c = threadIdx.x;
    int r0 = n * HWP + chunk * 512;
    float acc = 0.f;
    #pragma unroll 8
    for (int r = 0; r < 512; r++) acc += t[(size_t)(r0 + r) * CDIM + c];
    atomicAdd(&gsum[n * CDIM + c], acc);
}

__global__ __launch_bounds__(128)
void k_chatt(const float* __restrict__ gsum, float* __restrict__ g,
             const float* __restrict__ ca1w, const float* __restrict__ ca1b,
             const float* __restrict__ ca2w, const float* __restrict__ ca2b)
{
    __shared__ float gm[CDIM];
    __shared__ float r[7];
    int tid = threadIdx.x;
    for (int n = 0; n < NB; n++) {
        gm[tid] = gsum[n * CDIM + tid] * (1.0f / HWP);
        __syncthreads();
        if (tid < 7) {
            float s = ca1b[tid];
            for (int c = 0; c < CDIM; c++) s += gm[c] * ca1w[c * 7 + tid];
            r[tid] = fmaxf(s, 0.f);
        }
        __syncthreads();
        float s = ca2b[tid];
        #pragma unroll
        for (int jj = 0; jj < 7; jj++) s += r[jj] * ca2w[jj * CDIM + tid];
        g[n * CDIM + tid] = 1.0f / (1.0f + expf(-s));
        __syncthreads();
    }
}

// ---------------------------------------------------------------------------
// Neighborhood attention: one warp per (pixel, head). 4 warps / block (1 pixel).
// ---------------------------------------------------------------------------
__global__ __launch_bounds__(128)
void k_na(const float* __restrict__ qkv, const float* __restrict__ rpb,
          float* __restrict__ na)
{
    __shared__ float srpb[NHEAD][169];
    int row  = blockIdx.x;
    int h    = threadIdx.x >> 5;
    int lane = threadIdx.x & 31;

    for (int idx = lane; idx < 169; idx += 32)
        srpb[h][idx] = rpb[h * 169 + idx];
    __syncwarp();

    int n = row >> 12, p = row & 4095;
    int i = p >> 6, j = p & 63;
    int ni = i - 3; ni = ni < 0 ? 0 : (ni > 57 ? 57 : ni);
    int nj = j - 3; nj = nj < 0 ? 0 : (nj > 57 ? 57 : nj);

    float q = qkv[(size_t)row * 384 + h * DH + lane] * 0.17677669529663687f;
    int base = n * HWP;

    float attn[49];
    #pragma unroll
    for (int a = 0; a < KS; a++) {
        int ri = ni + a;
        #pragma unroll
        for (int bb = 0; bb < KS; bb++) {
            int rj = nj + bb;
            int krow = base + ri * 64 + rj;
            float kv = qkv[(size_t)krow * 384 + 128 + h * DH + lane];
            float s = q * kv;
            #pragma unroll
            for (int o = 16; o > 0; o >>= 1) s += __shfl_xor_sync(0xffffffffu, s, o);
            attn[a * KS + bb] = s + srpb[h][(ri - i + 6) * 13 + (rj - j + 6)];
        }
    }

    float m = attn[0];
    #pragma unroll
    for (int t = 1; t < 49; t++) m = fmaxf(m, attn[t]);
    float denom = 0.f;
    #pragma unroll
    for (int t = 0; t < 49; t++) { attn[t] = expf(attn[t] - m); denom += attn[t]; }
    float inv = 1.0f / denom;

    float out = 0.f;
    #pragma unroll
    for (int a = 0; a < KS; a++) {
        int ri = ni + a;
        #pragma unroll
        for (int bb = 0; bb < KS; bb++) {
            int rj = nj + bb;
            int vrow = base + ri * 64 + rj;
            float vv = qkv[(size_t)vrow * 384 + 256 + h * DH + lane];
            out = fmaf(attn[a * KS + bb] * inv, vv, out);
        }
    }
    na[(size_t)row * CDIM + h * DH + lane] = out;
}

// ---------------------------------------------------------------------------
// LayerNorm2 (row-major input): 1 warp / row, 8 rows / block
// ---------------------------------------------------------------------------
__global__ __launch_bounds__(256)
void k_ln2(const float* __restrict__ x2, float* __restrict__ xn2,
           const float* __restrict__ w, const float* __restrict__ b)
{
    int row  = blockIdx.x * 8 + (threadIdx.x >> 5);
    int lane = threadIdx.x & 31;
    const float4* xp = (const float4*)(x2 + (size_t)row * CDIM);
    float4 v = xp[lane];
    float sum = v.x + v.y + v.z + v.w;
    float sq  = v.x * v.x + v.y * v.y + v.z * v.z + v.w * v.w;
    #pragma unroll
    for (int o = 16; o > 0; o >>= 1) {
        sum += __shfl_xor_sync(0xffffffffu, sum, o);
        sq  += __shfl_xor_sync(0xffffffffu, sq, o);
    }
    float mu = sum * (1.0f / CDIM);
    float rs = rsqrtf(sq * (1.0f / CDIM) - mu * mu + 1e-5f);
    int c = lane * 4;
    float4 o4;
    o4.x = (v.x - mu) * rs * w[c + 0] + b[c + 0];
    o4.y = (v.y - mu) * rs * w[c + 1] + b[c + 1];
    o4.z = (v.z - mu) * rs * w[c + 2] + b[c + 2];
    o4.w = (v.w - mu) * rs * w[c + 3] + b[c + 3];
    ((float4*)(xn2 + (size_t)row * CDIM))[lane] = o4;
}

// ---------------------------------------------------------------------------
// Launch
// ---------------------------------------------------------------------------
extern "C" void kernel_launch(void* const* d_in, const int* in_sizes, int n_in,
                              void* d_out, int out_size)
{
    const float* x      = (const float*)d_in[0];
    const float* ln1_w  = (const float*)d_in[1];
    const float* ln1_b  = (const float*)d_in[2];
    const float* ln2_w  = (const float*)d_in[3];
    const float* ln2_b  = (const float*)d_in[4];
    const float* qkv_w  = (const float*)d_in[5];
    const float* qkv_b  = (const float*)d_in[6];
    const float* proj_w = (const float*)d_in[7];
    const float* proj_b = (const float*)d_in[8];
    const float* rpb    = (const float*)d_in[9];
    const float* conv1_w= (const float*)d_in[10];
    const float* conv1_b= (const float*)d_in[11];
    const float* conv2_w= (const float*)d_in[12];
    const float* conv2_b= (const float*)d_in[13];
    const float* ca1_w  = (const float*)d_in[14];
    const float* ca1_b  = (const float*)d_in[15];
    const float* ca2_w  = (const float*)d_in[16];
    const float* ca2_b  = (const float*)d_in[17];
    const float* fc1_w  = (const float*)d_in[18];
    const float* fc1_b  = (const float*)d_in[19];
    const float* fc2_w  = (const float*)d_in[20];
    const float* fc2_b  = (const float*)d_in[21];
    float* out = (float*)d_out;

    float* scr = nullptr;
    cudaGetSymbolAddress((void**)&scr, d_scratch);
    float* xs   = scr + OFF_XS;
    float* xn   = scr + OFF_XN;
    float* qkv  = scr + OFF_QKV;
    float* t1   = scr + OFF_T1;
    float* t    = scr + OFF_T;
    float* na   = scr + OFF_NA;
    float* x2   = scr + OFF_X2;
    float* xn2  = scr + OFF_XN2;
    float* h1   = scr + OFF_H1;
    float* gsum = scr + OFF_GSUM;
    float* g    = scr + OFF_G;

    // 1. transpose + LN1
    k_transpose_ln<<<ROWS / 32, 128>>>(x, ln1_w, ln1_b, xs, xn);
    // 2. zero channel-attention accumulator
    k_zero<<<1, 512>>>(gsum);
    // 3. qkv GEMM: 16384 x 384 x 128
    k_gemm<EPI_NONE><<<dim3(6, ROWS / 128), 256>>>(xn, qkv_w, qkv_b, qkv,
                                                   ROWS, 384, 128, nullptr, nullptr, nullptr);
    // 4. conv1 + gelu: 16384 x 32 x 128
    k_gemm<EPI_GELU><<<dim3(1, ROWS / 128), 256>>>(xn, conv1_w, conv1_b, t1,
                                                   ROWS, 32, 128, nullptr, nullptr, nullptr);
    // 5. conv2: 16384 x 128 x 32
    k_gemm<EPI_NONE><<<dim3(2, ROWS / 128), 256>>>(t1, conv2_w, conv2_b, t,
                                                   ROWS, 128, 32, nullptr, nullptr, nullptr);
    // 6. spatial mean of t per batch
    k_gmean<<<dim3(NB, 8), 128>>>(t, gsum);
    // 7. channel attention gates
    k_chatt<<<1, 128>>>(gsum, g, ca1_w, ca1_b, ca2_w, ca2_b);
    // 8. neighborhood attention
    k_na<<<ROWS, 128>>>(qkv, rpb, na);
    // 9. proj GEMM + residual combine -> x2
    k_gemm<EPI_X2><<<dim3(2, ROWS / 128), 256>>>(na, proj_w, proj_b, x2,
                                                 ROWS, 128, 128, xs, t, g);
    // 10. LN2
    k_ln2<<<ROWS / 8, 256>>>(x2, xn2, ln2_w, ln2_b);
    // 11. fc1 + gelu: 16384 x 512 x 128
    k_gemm<EPI_GELU><<<dim3(8, ROWS / 128), 256>>>(xn2, fc1_w, fc1_b, h1,
                                                   ROWS, 512, 128, nullptr, nullptr, nullptr);
    // 12. fc2 + residual, write NCHW output
    k_gemm<EPI_OUT><<<dim3(2, ROWS / 128), 256>>>(h1, fc2_w, fc2_b, out,
                                                  ROWS, 128, 512, x2, nullptr, nullptr);
}

// round 2
// speedup vs baseline: 1.3133x; 1.3133x over previous
#include <cuda_runtime.h>
#include <math.h>
#include <stdint.h>

// ---------------------------------------------------------------------------
// Problem constants
// ---------------------------------------------------------------------------
#define NB    4
#define CDIM  128
#define HWP   4096           // 64*64
#define ROWS  (NB * HWP)     // 16384
#define NHEAD 4
#define DH    32
#define KS    7

// Scratch arena layout (floats)
#define OFF_XS    0u
#define OFF_XN    2097152u            // 16384*128
#define OFF_QKV   4194304u            // len 16384*384
#define OFF_T1    10485760u           // len 16384*32
#define OFF_T     11010048u           // len 16384*128
#define OFF_NA    13107200u
#define OFF_X2    15204352u
#define OFF_XN2   17301504u
#define OFF_H1    19398656u           // len 16384*512
#define OFF_GSUM  27787264u           // 512
#define OFF_G     27787776u           // 512
#define SCRATCH_FLOATS 27788288u

__device__ float d_scratch[SCRATCH_FLOATS];

__device__ __forceinline__ float gelu_exact(float x) {
    return 0.5f * x * (1.0f + erff(x * 0.7071067811865476f));
}

__device__ __forceinline__ uint32_t f2tf32(float f) {
    uint32_t r;
    asm("cvt.rna.tf32.f32 %0, %1;" : "=r"(r) : "f"(f));
    return r;
}

__device__ __forceinline__ void mma_tf32(float d[4], const uint32_t a[4], const uint32_t b[2]) {
    asm volatile(
        "mma.sync.aligned.m16n8k8.row.col.f32.tf32.tf32.f32 "
        "{%0,%1,%2,%3},{%4,%5,%6,%7},{%8,%9},{%0,%1,%2,%3};\n"
        : "+f"(d[0]), "+f"(d[1]), "+f"(d[2]), "+f"(d[3])
        : "r"(a[0]), "r"(a[1]), "r"(a[2]), "r"(a[3]), "r"(b[0]), "r"(b[1]));
}

// ---------------------------------------------------------------------------
// Kernel 1: NCHW -> NHWC transpose + LayerNorm1.  32 pixels per block.
// ---------------------------------------------------------------------------
__global__ __launch_bounds__(128)
void k_transpose_ln(const float* __restrict__ x,
                    const float* __restrict__ w, const float* __restrict__ b,
                    float* __restrict__ xs, float* __restrict__ xn)
{
    __shared__ float s[32][129];
    __shared__ float smu[32], srs[32];
    int tid = threadIdx.x;
    int row0 = blockIdx.x * 32;
    int n  = row0 >> 12;
    int p0 = row0 & 4095;
    int pl = tid & 31;
    int cg = tid >> 5;       // 0..3

    #pragma unroll 4
    for (int it = 0; it < 32; it++) {
        int c = it * 4 + cg;
        s[pl][c] = x[((size_t)(n * CDIM + c) << 12) + p0 + pl];
    }
    __syncthreads();

    if (tid < 32) {
        float sum = 0.f, sq = 0.f;
        #pragma unroll 8
        for (int c = 0; c < CDIM; c++) { float v = s[tid][c]; sum += v; sq += v * v; }
        float mu  = sum * (1.0f / CDIM);
        float var = sq * (1.0f / CDIM) - mu * mu;
        smu[tid] = mu;
        srs[tid] = rsqrtf(var + 1e-5f);
    }
    __syncthreads();

    float wc = w[tid], bc = b[tid];
    #pragma unroll 4
    for (int it = 0; it < 32; it++) {
        float v = s[it][tid];
        size_t o = (size_t)(row0 + it) * CDIM + tid;
        xs[o] = v;
        xn[o] = (v - smu[it]) * srs[it] * wc + bc;
    }
}

// ---------------------------------------------------------------------------
// tf32 tensor-core GEMM: C[M,N] = A[M,K] @ B[K,N] + bias, with epilogues.
// BM=128, BK=32, BN=128 (or 32). 256 threads = 8 warps.
// ---------------------------------------------------------------------------
#define EPI_NONE 0
#define EPI_GELU 1
#define EPI_X2   2   // x2 = acc+bias + e1(xs) + e2(t)*e3(g[batch])*0.02
#define EPI_OUT  3   // out NCHW = acc+bias + e1(x2)

template<int EPI>
__device__ __forceinline__ void epi_write(float* __restrict__ C, int row, int col,
                                          int N, float v,
                                          const float* __restrict__ e1,
                                          const float* __restrict__ e2,
                                          const float* __restrict__ e3)
{
    if (EPI == EPI_GELU) {
        C[(size_t)row * N + col] = gelu_exact(v);
    } else if (EPI == EPI_NONE) {
        C[(size_t)row * N + col] = v;
    } else if (EPI == EPI_X2) {
        int bn = row >> 12;
        v += e1[(size_t)row * CDIM + col]
           + e2[(size_t)row * CDIM + col] * e3[bn * CDIM + col] * 0.02f;
        C[(size_t)row * CDIM + col] = v;
    } else { // EPI_OUT: write NCHW
        v += e1[(size_t)row * CDIM + col];
        int bn = row >> 12, p = row & 4095;
        C[((size_t)(bn * CDIM + col) << 12) + p] = v;
    }
}

template<int BN, int EPI>
__global__ __launch_bounds__(256)
void k_mma(const float* __restrict__ A, const float* __restrict__ B,
           const float* __restrict__ bias, float* __restrict__ C,
           int M, int N, int K,
           const float* __restrict__ e1, const float* __restrict__ e2,
           const float* __restrict__ e3)
{
    constexpr int BM = 128, BK = 32;
    constexpr int WM = (BN == 128) ? 2 : 8;     // warps along M
    constexpr int WN = 8 / WM;                  // warps along N
    constexpr int MT = BM / (WM * 16);          // m16 tiles per warp
    constexpr int NT = BN / (WN * 8);           // n8 tiles per warp
    constexpr int ASTRIDE = BK + 4;             // %32==4 -> conflict-free frag reads
    constexpr int BSTRIDE = BN + 8;             // %32==8 -> conflict-free frag reads

    __shared__ uint32_t As[BM][ASTRIDE];
    __shared__ uint32_t Bs[BK][BSTRIDE];

    int tid  = threadIdx.x;
    int lane = tid & 31;
    int warp = tid >> 5;
    int wm = warp % WM, wn = warp / WM;
    int m0 = blockIdx.y * BM, n0 = blockIdx.x * BN;
    int grp = lane >> 2, qk = lane & 3;

    float d[MT][NT][4];
    #pragma unroll
    for (int mt = 0; mt < MT; mt++)
        #pragma unroll
        for (int nt = 0; nt < NT; nt++)
            #pragma unroll
            for (int i = 0; i < 4; i++) d[mt][nt][i] = 0.f;

    int arow = tid >> 1;
    int kseg = (tid & 1) * 16;

    for (int k0 = 0; k0 < K; k0 += BK) {
        // ---- load A tile (128 x 32), convert to tf32 ----
        const float* Ap = A + (size_t)(m0 + arow) * K + k0 + kseg;
        #pragma unroll
        for (int i = 0; i < 4; i++) {
            float4 v = *(const float4*)(Ap + i * 4);
            As[arow][kseg + i * 4 + 0] = f2tf32(v.x);
            As[arow][kseg + i * 4 + 1] = f2tf32(v.y);
            As[arow][kseg + i * 4 + 2] = f2tf32(v.z);
            As[arow][kseg + i * 4 + 3] = f2tf32(v.w);
        }
        // ---- load B tile (32 x BN), convert to tf32 ----
        if (BN == 128) {
            int brow = tid >> 3, bcol = (tid & 7) * 16;
            const float* Bp = B + (size_t)(k0 + brow) * N + n0 + bcol;
            #pragma unroll
            for (int i = 0; i < 4; i++) {
                float4 v = *(const float4*)(Bp + i * 4);
                Bs[brow][bcol + i * 4 + 0] = f2tf32(v.x);
                Bs[brow][bcol + i * 4 + 1] = f2tf32(v.y);
                Bs[brow][bcol + i * 4 + 2] = f2tf32(v.z);
                Bs[brow][bcol + i * 4 + 3] = f2tf32(v.w);
            }
        } else {
            int brow = tid >> 3, bcol = (tid & 7) * 4;
            float4 v = *(const float4*)(B + (size_t)(k0 + brow) * N + n0 + bcol);
            Bs[brow][bcol + 0] = f2tf32(v.x);
            Bs[brow][bcol + 1] = f2tf32(v.y);
            Bs[brow][bcol + 2] = f2tf32(v.z);
            Bs[brow][bcol + 3] = f2tf32(v.w);
        }
        __syncthreads();

        #pragma unroll
        for (int kk = 0; kk < BK; kk += 8) {
            uint32_t af[MT][4];
            uint32_t bf[NT][2];
            #pragma unroll
            for (int mt = 0; mt < MT; mt++) {
                int r = wm * (MT * 16) + mt * 16 + grp;
                af[mt][0] = As[r][kk + qk];
                af[mt][1] = As[r + 8][kk + qk];
                af[mt][2] = As[r][kk + qk + 4];
                af[mt][3] = As[r + 8][kk + qk + 4];
            }
            #pragma unroll
            for (int nt = 0; nt < NT; nt++) {
                int cidx = wn * (NT * 8) + nt * 8 + grp;
                bf[nt][0] = Bs[kk + qk][cidx];
                bf[nt][1] = Bs[kk + qk + 4][cidx];
            }
            #pragma unroll
            for (int mt = 0; mt < MT; mt++)
                #pragma unroll
                for (int nt = 0; nt < NT; nt++)
                    mma_tf32(d[mt][nt], af[mt], bf[nt]);
        }
        __syncthreads();
    }

    // ---- epilogue ----
    #pragma unroll
    for (int mt = 0; mt < MT; mt++) {
        int rbase = m0 + wm * (MT * 16) + mt * 16 + grp;
        #pragma unroll
        for (int nt = 0; nt < NT; nt++) {
            int cbase = n0 + wn * (NT * 8) + nt * 8 + 2 * qk;
            float b0 = bias[cbase], b1 = bias[cbase + 1];
            epi_write<EPI>(C, rbase,     cbase,     N, d[mt][nt][0] + b0, e1, e2, e3);
            epi_write<EPI>(C, rbase,     cbase + 1, N, d[mt][nt][1] + b1, e1, e2, e3);
            epi_write<EPI>(C, rbase + 8, cbase,     N, d[mt][nt][2] + b0, e1, e2, e3);
            epi_write<EPI>(C, rbase + 8, cbase + 1, N, d[mt][nt][3] + b1, e1, e2, e3);
        }
    }
}

// ---------------------------------------------------------------------------
// Channel-attention reductions
// ---------------------------------------------------------------------------
__global__ void k_zero(float* __restrict__ gsum) {
    gsum[threadIdx.x] = 0.f;   // 512 threads
}

__global__ __launch_bounds__(128)
void k_gmean(const float* __restrict__ t, float* __restrict__ gsum)
{
    int n = blockIdx.x, chunk = blockIdx.y;
    int c = threadIdx.x;
    int r0 = n * HWP + chunk * 512;
    float acc = 0.f;
    #pragma unroll 8
    for (int r = 0; r < 512; r++) acc += t[(size_t)(r0 + r) * CDIM + c];
    atomicAdd(&gsum[n * CDIM + c], acc);
}

__global__ __launch_bounds__(128)
void k_chatt(const float* __restrict__ gsum, float* __restrict__ g,
             const float* __restrict__ ca1w, const float* __restrict__ ca1b,
             const float* __restrict__ ca2w, const float* __restrict__ ca2b)
{
    __shared__ float gm[CDIM];
    __shared__ float r[7];
    int tid = threadIdx.x;
    for (int n = 0; n < NB; n++) {
        gm[tid] = gsum[n * CDIM + tid] * (1.0f / HWP);
        __syncthreads();
        if (tid < 7) {
            float s = ca1b[tid];
            for (int c = 0; c < CDIM; c++) s += gm[c] * ca1w[c * 7 + tid];
            r[tid] = fmaxf(s, 0.f);
        }
        __syncthreads();
        float s = ca2b[tid];
        #pragma unroll
        for (int jj = 0; jj < 7; jj++) s += r[jj] * ca2w[jj * CDIM + tid];
        g[n * CDIM + tid] = 1.0f / (1.0f + expf(-s));
        __syncthreads();
    }
}

// ---------------------------------------------------------------------------
// Neighborhood attention: one warp per (pixel, head). 4 warps / block (1 pixel).
// ---------------------------------------------------------------------------
__global__ __launch_bounds__(128)
void k_na(const float* __restrict__ qkv, const float* __restrict__ rpb,
          float* __restrict__ na)
{
    __shared__ float srpb[NHEAD][169];
    int row  = blockIdx.x;
    int h    = threadIdx.x >> 5;
    int lane = threadIdx.x & 31;

    for (int idx = lane; idx < 169; idx += 32)
        srpb[h][idx] = rpb[h * 169 + idx];
    __syncwarp();

    int n = row >> 12, p = row & 4095;
    int i = p >> 6, j = p & 63;
    int ni = i - 3; ni = ni < 0 ? 0 : (ni > 57 ? 57 : ni);
    int nj = j - 3; nj = nj < 0 ? 0 : (nj > 57 ? 57 : nj);

    float q = qkv[(size_t)row * 384 + h * DH + lane] * 0.17677669529663687f;
    int base = n * HWP;

    float attn[49];
    #pragma unroll
    for (int a = 0; a < KS; a++) {
        int ri = ni + a;
        #pragma unroll
        for (int bb = 0; bb < KS; bb++) {
            int rj = nj + bb;
            int krow = base + ri * 64 + rj;
            float kv = qkv[(size_t)krow * 384 + 128 + h * DH + lane];
            float s = q * kv;
            #pragma unroll
            for (int o = 16; o > 0; o >>= 1) s += __shfl_xor_sync(0xffffffffu, s, o);
            attn[a * KS + bb] = s + srpb[h][(ri - i + 6) * 13 + (rj - j + 6)];
        }
    }

    float m = attn[0];
    #pragma unroll
    for (int t = 1; t < 49; t++) m = fmaxf(m, attn[t]);
    float denom = 0.f;
    #pragma unroll
    for (int t = 0; t < 49; t++) { attn[t] = expf(attn[t] - m); denom += attn[t]; }
    float inv = 1.0f / denom;

    float out = 0.f;
    #pragma unroll
    for (int a = 0; a < KS; a++) {
        int ri = ni + a;
        #pragma unroll
        for (int bb = 0; bb < KS; bb++) {
            int rj = nj + bb;
            int vrow = base + ri * 64 + rj;
            float vv = qkv[(size_t)vrow * 384 + 256 + h * DH + lane];
            out = fmaf(attn[a * KS + bb] * inv, vv, out);
        }
    }
    na[(size_t)row * CDIM + h * DH + lane] = out;
}

// ---------------------------------------------------------------------------
// LayerNorm2 (row-major input): 1 warp / row, 8 rows / block
// ---------------------------------------------------------------------------
__global__ __launch_bounds__(256)
void k_ln2(const float* __restrict__ x2, float* __restrict__ xn2,
           const float* __restrict__ w, const float* __restrict__ b)
{
    int row  = blockIdx.x * 8 + (threadIdx.x >> 5);
    int lane = threadIdx.x & 31;
    const float4* xp = (const float4*)(x2 + (size_t)row * CDIM);
    float4 v = xp[lane];
    float sum = v.x + v.y + v.z + v.w;
    float sq  = v.x * v.x + v.y * v.y + v.z * v.z + v.w * v.w;
    #pragma unroll
    for (int o = 16; o > 0; o >>= 1) {
        sum += __shfl_xor_sync(0xffffffffu, sum, o);
        sq  += __shfl_xor_sync(0xffffffffu, sq, o);
    }
    float mu = sum * (1.0f / CDIM);
    float rs = rsqrtf(sq * (1.0f / CDIM) - mu * mu + 1e-5f);
    int c = lane * 4;
    float4 o4;
    o4.x = (v.x - mu) * rs * w[c + 0] + b[c + 0];
    o4.y = (v.y - mu) * rs * w[c + 1] + b[c + 1];
    o4.z = (v.z - mu) * rs * w[c + 2] + b[c + 2];
    o4.w = (v.w - mu) * rs * w[c + 3] + b[c + 3];
    ((float4*)(xn2 + (size_t)row * CDIM))[lane] = o4;
}

// ---------------------------------------------------------------------------
// Launch
// ---------------------------------------------------------------------------
extern "C" void kernel_launch(void* const* d_in, const int* in_sizes, int n_in,
                              void* d_out, int out_size)
{
    const float* x      = (const float*)d_in[0];
    const float* ln1_w  = (const float*)d_in[1];
    const float* ln1_b  = (const float*)d_in[2];
    const float* ln2_w  = (const float*)d_in[3];
    const float* ln2_b  = (const float*)d_in[4];
    const float* qkv_w  = (const float*)d_in[5];
    const float* qkv_b  = (const float*)d_in[6];
    const float* proj_w = (const float*)d_in[7];
    const float* proj_b = (const float*)d_in[8];
    const float* rpb    = (const float*)d_in[9];
    const float* conv1_w= (const float*)d_in[10];
    const float* conv1_b= (const float*)d_in[11];
    const float* conv2_w= (const float*)d_in[12];
    const float* conv2_b= (const float*)d_in[13];
    const float* ca1_w  = (const float*)d_in[14];
    const float* ca1_b  = (const float*)d_in[15];
    const float* ca2_w  = (const float*)d_in[16];
    const float* ca2_b  = (const float*)d_in[17];
    const float* fc1_w  = (const float*)d_in[18];
    const float* fc1_b  = (const float*)d_in[19];
    const float* fc2_w  = (const float*)d_in[20];
    const float* fc2_b  = (const float*)d_in[21];
    float* out = (float*)d_out;

    float* scr = nullptr;
    cudaGetSymbolAddress((void**)&scr, d_scratch);
    float* xs   = scr + OFF_XS;
    float* xn   = scr + OFF_XN;
    float* qkv  = scr + OFF_QKV;
    float* t1   = scr + OFF_T1;
    float* t    = scr + OFF_T;
    float* na   = scr + OFF_NA;
    float* x2   = scr + OFF_X2;
    float* xn2  = scr + OFF_XN2;
    float* h1   = scr + OFF_H1;
    float* gsum = scr + OFF_GSUM;
    float* g    = scr + OFF_G;

    // 1. transpose + LN1
    k_transpose_ln<<<ROWS / 32, 128>>>(x, ln1_w, ln1_b, xs, xn);
    // 2. zero channel-attention accumulator
    k_zero<<<1, 512>>>(gsum);
    // 3. qkv GEMM: 16384 x 384 x 128
    k_mma<128, EPI_NONE><<<dim3(3, ROWS / 128), 256>>>(xn, qkv_w, qkv_b, qkv,
                                                       ROWS, 384, 128, nullptr, nullptr, nullptr);
    // 4. conv1 + gelu: 16384 x 32 x 128
    k_mma<32, EPI_GELU><<<dim3(1, ROWS / 128), 256>>>(xn, conv1_w, conv1_b, t1,
                                                      ROWS, 32, 128, nullptr, nullptr, nullptr);
    // 5. conv2: 16384 x 128 x 32
    k_mma<128, EPI_NONE><<<dim3(1, ROWS / 128), 256>>>(t1, conv2_w, conv2_b, t,
                                                       ROWS, 128, 32, nullptr, nullptr, nullptr);
    // 6. spatial mean of t per batch
    k_gmean<<<dim3(NB, 8), 128>>>(t, gsum);
    // 7. channel attention gates
    k_chatt<<<1, 128>>>(gsum, g, ca1_w, ca1_b, ca2_w, ca2_b);
    // 8. neighborhood attention
    k_na<<<ROWS, 128>>>(qkv, rpb, na);
    // 9. proj GEMM + residual combine -> x2
    k_mma<128, EPI_X2><<<dim3(1, ROWS / 128), 256>>>(na, proj_w, proj_b, x2,
                                                     ROWS, 128, 128, xs, t, g);
    // 10. LN2
    k_ln2<<<ROWS / 8, 256>>>(x2, xn2, ln2_w, ln2_b);
    // 11. fc1 + gelu: 16384 x 512 x 128
    k_mma<128, EPI_GELU><<<dim3(4, ROWS / 128), 256>>>(xn2, fc1_w, fc1_b, h1,
                                                       ROWS, 512, 128, nullptr, nullptr, nullptr);
    // 12. fc2 + residual, write NCHW output
    k_mma<128, EPI_OUT><<<dim3(1, ROWS / 128), 256>>>(h1, fc2_w, fc2_b, out,
                                                      ROWS, 128, 512, x2, nullptr, nullptr);
}

// round 3
// speedup vs baseline: 1.3412x; 1.0213x over previous
#include <cuda_runtime.h>
#include <math.h>
#include <stdint.h>

// ---------------------------------------------------------------------------
// Problem constants
// ---------------------------------------------------------------------------
#define NB    4
#define CDIM  128
#define HWP   4096           // 64*64
#define ROWS  (NB * HWP)     // 16384
#define NHEAD 4
#define DH    32
#define KS    7

// Scratch arena layout (floats)
#define OFF_XS    0u
#define OFF_XN    2097152u            // 16384*128
#define OFF_QKV   4194304u            // len 16384*384
#define OFF_T1    10485760u           // len 16384*32
#define OFF_T     11010048u           // len 16384*128
#define OFF_NA    13107200u
#define OFF_X2    15204352u
#define OFF_XN2   17301504u
#define OFF_H1    19398656u           // len 16384*512
#define OFF_GSUM  27787264u           // 512
#define OFF_G     27787776u           // 512
#define SCRATCH_FLOATS 27788288u

__device__ float d_scratch[SCRATCH_FLOATS];

__device__ __forceinline__ float gelu_exact(float x) {
    return 0.5f * x * (1.0f + erff(x * 0.7071067811865476f));
}

__device__ __forceinline__ uint32_t f2tf32(float f) {
    uint32_t r;
    asm("cvt.rna.tf32.f32 %0, %1;" : "=r"(r) : "f"(f));
    return r;
}

__device__ __forceinline__ void mma_tf32(float d[4], const uint32_t a[4], const uint32_t b[2]) {
    asm volatile(
        "mma.sync.aligned.m16n8k8.row.col.f32.tf32.tf32.f32 "
        "{%0,%1,%2,%3},{%4,%5,%6,%7},{%8,%9},{%0,%1,%2,%3};\n"
        : "+f"(d[0]), "+f"(d[1]), "+f"(d[2]), "+f"(d[3])
        : "r"(a[0]), "r"(a[1]), "r"(a[2]), "r"(a[3]), "r"(b[0]), "r"(b[1]));
}

// ---------------------------------------------------------------------------
// Kernel 1: NCHW -> NHWC transpose + LayerNorm1.  32 pixels per block.
// Block 0 additionally zeros the channel-attention accumulator.
// ---------------------------------------------------------------------------
__global__ __launch_bounds__(128)
void k_transpose_ln(const float* __restrict__ x,
                    const float* __restrict__ w, const float* __restrict__ b,
                    float* __restrict__ xs, float* __restrict__ xn,
                    float* __restrict__ gsum)
{
    __shared__ float s[32][129];
    __shared__ float smu[32], srs[32];
    int tid = threadIdx.x;
    if (blockIdx.x == 0) {
        #pragma unroll
        for (int i = 0; i < 4; i++) gsum[tid + i * 128] = 0.f;
    }
    int row0 = blockIdx.x * 32;
    int n  = row0 >> 12;
    int p0 = row0 & 4095;
    int pl = tid & 31;
    int cg = tid >> 5;       // 0..3

    #pragma unroll 4
    for (int it = 0; it < 32; it++) {
        int c = it * 4 + cg;
        s[pl][c] = x[((size_t)(n * CDIM + c) << 12) + p0 + pl];
    }
    __syncthreads();

    if (tid < 32) {
        float sum = 0.f, sq = 0.f;
        #pragma unroll 8
        for (int c = 0; c < CDIM; c++) { float v = s[tid][c]; sum += v; sq += v * v; }
        float mu  = sum * (1.0f / CDIM);
        float var = sq * (1.0f / CDIM) - mu * mu;
        smu[tid] = mu;
        srs[tid] = rsqrtf(var + 1e-5f);
    }
    __syncthreads();

    float wc = w[tid], bc = b[tid];
    #pragma unroll 4
    for (int it = 0; it < 32; it++) {
        float v = s[it][tid];
        size_t o = (size_t)(row0 + it) * CDIM + tid;
        xs[o] = v;
        xn[o] = (v - smu[it]) * srs[it] * wc + bc;
    }
}

// ---------------------------------------------------------------------------
// tf32 tensor-core GEMM: C[M,N] = A[M,K] @ B[K,N] + bias, with epilogues.
// BM=64, BK=32, BN=64 (or 32). 128 threads = 4 warps (2x2 warp grid).
// ---------------------------------------------------------------------------
#define EPI_NONE 0
#define EPI_GELU 1
#define EPI_X2   2   // x2 = acc+bias + e1(xs) + e2(t)*e3(g[batch])*0.02
#define EPI_OUT  3   // out NCHW = acc+bias + e1(x2)

template<int EPI>
__device__ __forceinline__ void epi_write(float* __restrict__ C, int row, int col,
                                          int N, float v,
                                          const float* __restrict__ e1,
                                          const float* __restrict__ e2,
                                          const float* __restrict__ e3)
{
    if (EPI == EPI_GELU) {
        C[(size_t)row * N + col] = gelu_exact(v);
    } else if (EPI == EPI_NONE) {
        C[(size_t)row * N + col] = v;
    } else if (EPI == EPI_X2) {
        int bn = row >> 12;
        v += e1[(size_t)row * CDIM + col]
           + e2[(size_t)row * CDIM + col] * e3[bn * CDIM + col] * 0.02f;
        C[(size_t)row * CDIM + col] = v;
    } else { // EPI_OUT: write NCHW
        v += e1[(size_t)row * CDIM + col];
        int bn = row >> 12, p = row & 4095;
        C[((size_t)(bn * CDIM + col) << 12) + p] = v;
    }
}

template<int BN, int EPI>
__global__ __launch_bounds__(128)
void k_mma(const float* __restrict__ A, const float* __restrict__ B,
           const float* __restrict__ bias, float* __restrict__ C,
           int M, int N, int K,
           const float* __restrict__ e1, const float* __restrict__ e2,
           const float* __restrict__ e3)
{
    constexpr int BM = 64, BK = 32;
    constexpr int MT = 2;            // 32 rows per warp
    constexpr int NT = BN / 16;      // 64 -> 4 (32 cols/warp), 32 -> 2
    constexpr int ASTRIDE = BK + 4;  // %32==4
    constexpr int BSTRIDE = BN + 8;  // %32==8

    __shared__ uint32_t As[BM][ASTRIDE];
    __shared__ uint32_t Bs[BK][BSTRIDE];

    int tid  = threadIdx.x;
    int lane = tid & 31;
    int warp = tid >> 5;
    int wm = warp & 1, wn = warp >> 1;
    int m0 = blockIdx.y * BM, n0 = blockIdx.x * BN;
    int grp = lane >> 2, qk = lane & 3;

    float d[MT][NT][4];
    #pragma unroll
    for (int mt = 0; mt < MT; mt++)
        #pragma unroll
        for (int nt = 0; nt < NT; nt++)
            #pragma unroll
            for (int i = 0; i < 4; i++) d[mt][nt][i] = 0.f;

    int arow = tid >> 1;
    int kseg = (tid & 1) * 16;

    for (int k0 = 0; k0 < K; k0 += BK) {
        // ---- load A tile (64 x 32) ----
        const float* Ap = A + (size_t)(m0 + arow) * K + k0 + kseg;
        #pragma unroll
        for (int i = 0; i < 4; i++) {
            float4 v = *(const float4*)(Ap + i * 4);
            As[arow][kseg + i * 4 + 0] = f2tf32(v.x);
            As[arow][kseg + i * 4 + 1] = f2tf32(v.y);
            As[arow][kseg + i * 4 + 2] = f2tf32(v.z);
            As[arow][kseg + i * 4 + 3] = f2tf32(v.w);
        }
        // ---- load B tile (32 x BN) ----
        if (BN == 64) {
            int brow = tid >> 2, bcol = (tid & 3) * 16;
            const float* Bp = B + (size_t)(k0 + brow) * N + n0 + bcol;
            #pragma unroll
            for (int i = 0; i < 4; i++) {
                float4 v = *(const float4*)(Bp + i * 4);
                Bs[brow][bcol + i * 4 + 0] = f2tf32(v.x);
                Bs[brow][bcol + i * 4 + 1] = f2tf32(v.y);
                Bs[brow][bcol + i * 4 + 2] = f2tf32(v.z);
                Bs[brow][bcol + i * 4 + 3] = f2tf32(v.w);
            }
        } else {
            int brow = tid >> 2, bcol = (tid & 3) * 8;
            const float* Bp = B + (size_t)(k0 + brow) * N + n0 + bcol;
            #pragma unroll
            for (int i = 0; i < 2; i++) {
                float4 v = *(const float4*)(Bp + i * 4);
                Bs[brow][bcol + i * 4 + 0] = f2tf32(v.x);
                Bs[brow][bcol + i * 4 + 1] = f2tf32(v.y);
                Bs[brow][bcol + i * 4 + 2] = f2tf32(v.z);
                Bs[brow][bcol + i * 4 + 3] = f2tf32(v.w);
            }
        }
        __syncthreads();

        #pragma unroll
        for (int kk = 0; kk < BK; kk += 8) {
            uint32_t af[MT][4];
            uint32_t bf[NT][2];
            #pragma unroll
            for (int mt = 0; mt < MT; mt++) {
                int r = wm * 32 + mt * 16 + grp;
                af[mt][0] = As[r][kk + qk];
                af[mt][1] = As[r + 8][kk + qk];
                af[mt][2] = As[r][kk + qk + 4];
                af[mt][3] = As[r + 8][kk + qk + 4];
            }
            #pragma unroll
            for (int nt = 0; nt < NT; nt++) {
                int cidx = wn * (NT * 8) + nt * 8 + grp;
                bf[nt][0] = Bs[kk + qk][cidx];
                bf[nt][1] = Bs[kk + qk + 4][cidx];
            }
            #pragma unroll
            for (int mt = 0; mt < MT; mt++)
                #pragma unroll
                for (int nt = 0; nt < NT; nt++)
                    mma_tf32(d[mt][nt], af[mt], bf[nt]);
        }
        __syncthreads();
    }

    // ---- epilogue ----
    #pragma unroll
    for (int mt = 0; mt < MT; mt++) {
        int rbase = m0 + wm * 32 + mt * 16 + grp;
        #pragma unroll
        for (int nt = 0; nt < NT; nt++) {
            int cbase = n0 + wn * (NT * 8) + nt * 8 + 2 * qk;
            float b0 = bias[cbase], b1 = bias[cbase + 1];
            epi_write<EPI>(C, rbase,     cbase,     N, d[mt][nt][0] + b0, e1, e2, e3);
            epi_write<EPI>(C, rbase,     cbase + 1, N, d[mt][nt][1] + b1, e1, e2, e3);
            epi_write<EPI>(C, rbase + 8, cbase,     N, d[mt][nt][2] + b0, e1, e2, e3);
            epi_write<EPI>(C, rbase + 8, cbase + 1, N, d[mt][nt][3] + b1, e1, e2, e3);
        }
    }
}

// ---------------------------------------------------------------------------
// Channel-attention reductions
// ---------------------------------------------------------------------------
__global__ __launch_bounds__(128)
void k_gmean(const float* __restrict__ t, float* __restrict__ gsum)
{
    int n = blockIdx.x, chunk = blockIdx.y;
    int c = threadIdx.x;
    int r0 = n * HWP + chunk * 512;
    float acc = 0.f;
    #pragma unroll 8
    for (int r = 0; r < 512; r++) acc += t[(size_t)(r0 + r) * CDIM + c];
    atomicAdd(&gsum[n * CDIM + c], acc);
}

__global__ __launch_bounds__(128)
void k_chatt(const float* __restrict__ gsum, float* __restrict__ g,
             const float* __restrict__ ca1w, const float* __restrict__ ca1b,
             const float* __restrict__ ca2w, const float* __restrict__ ca2b)
{
    __shared__ float gm[CDIM];
    __shared__ float r[7];
    int tid = threadIdx.x;
    for (int n = 0; n < NB; n++) {
        gm[tid] = gsum[n * CDIM + tid] * (1.0f / HWP);
        __syncthreads();
        if (tid < 7) {
            float s = ca1b[tid];
            for (int c = 0; c < CDIM; c++) s += gm[c] * ca1w[c * 7 + tid];
            r[tid] = fmaxf(s, 0.f);
        }
        __syncthreads();
        float s = ca2b[tid];
        #pragma unroll
        for (int jj = 0; jj < 7; jj++) s += r[jj] * ca2w[jj * CDIM + tid];
        g[n * CDIM + tid] = 1.0f / (1.0f + expf(-s));
        __syncthreads();
    }
}

// ---------------------------------------------------------------------------
// Neighborhood attention, smem-tiled.
// Block = (8x8 pixel tile, batch, head). 256 threads = 8 warps; warp = 8 pixels.
// Two-phase window buffer: K first (scores -> smem), then V (output).
// ---------------------------------------------------------------------------
__global__ __launch_bounds__(256)
void k_na(const float* __restrict__ qkv, const float* __restrict__ rpb,
          float* __restrict__ na)
{
    __shared__ float skv[196][32];   // 14x14 window, 32 channels
    __shared__ float ssc[64][50];    // per-pixel scores (49, padded)
    __shared__ float srpb[169];

    int tid  = threadIdx.x;
    int lane = tid & 31;
    int warp = tid >> 5;

    int n = blockIdx.y >> 2;
    int h = blockIdx.y & 3;
    int ti = blockIdx.x >> 3, tj = blockIdx.x & 7;
    int i0 = ti * 8, j0 = tj * 8;
    int wi0 = i0 - 3; wi0 = wi0 < 0 ? 0 : (wi0 > 57 ? 57 : wi0);
    int wj0 = j0 - 3; wj0 = wj0 < 0 ? 0 : (wj0 > 57 ? 57 : wj0);

    if (tid < 169) srpb[tid] = rpb[h * 169 + tid];

    const float* qkv_base = qkv + (size_t)(n * HWP) * 384 + h * DH;

    // ---- phase 1: load K window ----
    #pragma unroll
    for (int idx = tid; idx < 196 * 32; idx += 256) {
        int r = idx >> 5, c = idx & 31;
        int gi = wi0 + r / 14; gi = gi > 63 ? 63 : gi;
        int gj = wj0 + r % 14; gj = gj > 63 ? 63 : gj;
        skv[r][c] = qkv_base[(size_t)(gi * 64 + gj) * 384 + 128 + c];
    }
    __syncthreads();

    // ---- phase 2: scores for this warp's 8 pixels ----
    int pix0 = warp * 8;
    #pragma unroll
    for (int pp = 0; pp < 8; pp++) {
        int p = pix0 + pp;
        int i = i0 + (p >> 3), j = j0 + (p & 7);
        int ni = i - 3; ni = ni < 0 ? 0 : (ni > 57 ? 57 : ni);
        int nj = j - 3; nj = nj < 0 ? 0 : (nj > 57 ? 57 : nj);
        float q = qkv_base[(size_t)(i * 64 + j) * 384 + lane] * 0.17677669529663687f;
        int nbase = (ni - wi0) * 14 + (nj - wj0);
        int bbase = (ni - i + 6) * 13 + (nj - j + 6);
        #pragma unroll
        for (int a = 0; a < KS; a++) {
            #pragma unroll
            for (int bcol = 0; bcol < KS; bcol++) {
                float s = q * skv[nbase + a * 14 + bcol][lane];
                #pragma unroll
                for (int o = 16; o > 0; o >>= 1) s += __shfl_xor_sync(0xffffffffu, s, o);
                if (lane == 0)
                    ssc[p][a * KS + bcol] = s + srpb[bbase + a * 13 + bcol];
            }
        }
    }
    __syncthreads();

    // ---- phase 3: overwrite window with V ----
    #pragma unroll
    for (int idx = tid; idx < 196 * 32; idx += 256) {
        int r = idx >> 5, c = idx & 31;
        int gi = wi0 + r / 14; gi = gi > 63 ? 63 : gi;
        int gj = wj0 + r % 14; gj = gj > 63 ? 63 : gj;
        skv[r][c] = qkv_base[(size_t)(gi * 64 + gj) * 384 + 256 + c];
    }
    __syncthreads();

    // ---- phase 4: softmax + V accumulate ----
    #pragma unroll
    for (int pp = 0; pp < 8; pp++) {
        int p = pix0 + pp;
        int i = i0 + (p >> 3), j = j0 + (p & 7);
        int ni = i - 3; ni = ni < 0 ? 0 : (ni > 57 ? 57 : ni);
        int nj = j - 3; nj = nj < 0 ? 0 : (nj > 57 ? 57 : nj);
        int nbase = (ni - wi0) * 14 + (nj - wj0);

        // warp-parallel max / exp / sum over 49 scores
        float a0 = ssc[p][lane];
        float a1 = (lane < 17) ? ssc[p][lane + 32] : -1e30f;
        float m = fmaxf(a0, a1);
        #pragma unroll
        for (int o = 16; o > 0; o >>= 1) m = fmaxf(m, __shfl_xor_sync(0xffffffffu, m, o));
        float e0 = __expf(a0 - m);
        float e1 = (lane < 17) ? __expf(a1 - m) : 0.f;
        float ps = e0 + e1;
        #pragma unroll
        for (int o = 16; o > 0; o >>= 1) ps += __shfl_xor_sync(0xffffffffu, ps, o);
        float inv = 1.0f / ps;
        ssc[p][lane] = e0 * inv;
        if (lane < 17) ssc[p][lane + 32] = e1 * inv;
        __syncwarp();

        float out = 0.f;
        #pragma unroll
        for (int a = 0; a < KS; a++) {
            #pragma unroll
            for (int bcol = 0; bcol < KS; bcol++) {
                out = fmaf(ssc[p][a * KS + bcol], skv[nbase + a * 14 + bcol][lane], out);
            }
        }
        na[(size_t)(n * HWP + i * 64 + j) * CDIM + h * DH + lane] = out;
    }
}

// ---------------------------------------------------------------------------
// LayerNorm2 (row-major input): 1 warp / row, 8 rows / block
// ---------------------------------------------------------------------------
__global__ __launch_bounds__(256)
void k_ln2(const float* __restrict__ x2, float* __restrict__ xn2,
           const float* __restrict__ w, const float* __restrict__ b)
{
    int row  = blockIdx.x * 8 + (threadIdx.x >> 5);
    int lane = threadIdx.x & 31;
    const float4* xp = (const float4*)(x2 + (size_t)row * CDIM);
    float4 v = xp[lane];
    float sum = v.x + v.y + v.z + v.w;
    float sq  = v.x * v.x + v.y * v.y + v.z * v.z + v.w * v.w;
    #pragma unroll
    for (int o = 16; o > 0; o >>= 1) {
        sum += __shfl_xor_sync(0xffffffffu, sum, o);
        sq  += __shfl_xor_sync(0xffffffffu, sq, o);
    }
    float mu = sum * (1.0f / CDIM);
    float rs = rsqrtf(sq * (1.0f / CDIM) - mu * mu + 1e-5f);
    int c = lane * 4;
    float4 o4;
    o4.x = (v.x - mu) * rs * w[c + 0] + b[c + 0];
    o4.y = (v.y - mu) * rs * w[c + 1] + b[c + 1];
    o4.z = (v.z - mu) * rs * w[c + 2] + b[c + 2];
    o4.w = (v.w - mu) * rs * w[c + 3] + b[c + 3];
    ((float4*)(xn2 + (size_t)row * CDIM))[lane] = o4;
}

// ---------------------------------------------------------------------------
// Launch
// ---------------------------------------------------------------------------
extern "C" void kernel_launch(void* const* d_in, const int* in_sizes, int n_in,
                              void* d_out, int out_size)
{
    const float* x      = (const float*)d_in[0];
    const float* ln1_w  = (const float*)d_in[1];
    const float* ln1_b  = (const float*)d_in[2];
    const float* ln2_w  = (const float*)d_in[3];
    const float* ln2_b  = (const float*)d_in[4];
    const float* qkv_w  = (const float*)d_in[5];
    const float* qkv_b  = (const float*)d_in[6];
    const float* proj_w = (const float*)d_in[7];
    const float* proj_b = (const float*)d_in[8];
    const float* rpb    = (const float*)d_in[9];
    const float* conv1_w= (const float*)d_in[10];
    const float* conv1_b= (const float*)d_in[11];
    const float* conv2_w= (const float*)d_in[12];
    const float* conv2_b= (const float*)d_in[13];
    const float* ca1_w  = (const float*)d_in[14];
    const float* ca1_b  = (const float*)d_in[15];
    const float* ca2_w  = (const float*)d_in[16];
    const float* ca2_b  = (const float*)d_in[17];
    const float* fc1_w  = (const float*)d_in[18];
    const float* fc1_b  = (const float*)d_in[19];
    const float* fc2_w  = (const float*)d_in[20];
    const float* fc2_b  = (const float*)d_in[21];
    float* out = (float*)d_out;

    float* scr = nullptr;
    cudaGetSymbolAddress((void**)&scr, d_scratch);
    float* xs   = scr + OFF_XS;
    float* xn   = scr + OFF_XN;
    float* qkv  = scr + OFF_QKV;
    float* t1   = scr + OFF_T1;
    float* t    = scr + OFF_T;
    float* na   = scr + OFF_NA;
    float* x2   = scr + OFF_X2;
    float* xn2  = scr + OFF_XN2;
    float* h1   = scr + OFF_H1;
    float* gsum = scr + OFF_GSUM;
    float* g    = scr + OFF_G;

    // 1. transpose + LN1 (+ zero gsum)
    k_transpose_ln<<<ROWS / 32, 128>>>(x, ln1_w, ln1_b, xs, xn, gsum);
    // 2. qkv GEMM: 16384 x 384 x 128
    k_mma<64, EPI_NONE><<<dim3(6, ROWS / 64), 128>>>(xn, qkv_w, qkv_b, qkv,
                                                     ROWS, 384, 128, nullptr, nullptr, nullptr);
    // 3. conv1 + gelu: 16384 x 32 x 128
    k_mma<32, EPI_GELU><<<dim3(1, ROWS / 64), 128>>>(xn, conv1_w, conv1_b, t1,
                                                     ROWS, 32, 128, nullptr, nullptr, nullptr);
    // 4. conv2: 16384 x 128 x 32
    k_mma<64, EPI_NONE><<<dim3(2, ROWS / 64), 128>>>(t1, conv2_w, conv2_b, t,
                                                     ROWS, 128, 32, nullptr, nullptr, nullptr);
    // 5. spatial mean of t per batch
    k_gmean<<<dim3(NB, 8), 128>>>(t, gsum);
    // 6. channel attention gates
    k_chatt<<<1, 128>>>(gsum, g, ca1_w, ca1_b, ca2_w, ca2_b);
    // 7. neighborhood attention (tiled)
    k_na<<<dim3(64, NB * NHEAD), 256>>>(qkv, rpb, na);
    // 8. proj GEMM + residual combine -> x2
    k_mma<64, EPI_X2><<<dim3(2, ROWS / 64), 128>>>(na, proj_w, proj_b, x2,
                                                   ROWS, 128, 128, xs, t, g);
    // 9. LN2
    k_ln2<<<ROWS / 8, 256>>>(x2, xn2, ln2_w, ln2_b);
    // 10. fc1 + gelu: 16384 x 512 x 128
    k_mma<64, EPI_GELU><<<dim3(8, ROWS / 64), 128>>>(xn2, fc1_w, fc1_b, h1,
                                                     ROWS, 512, 128, nullptr, nullptr, nullptr);
    // 11. fc2 + residual, write NCHW output
    k_mma<64, EPI_OUT><<<dim3(2, ROWS / 64), 128>>>(h1, fc2_w, fc2_b, out,
                                                    ROWS, 128, 512, x2, nullptr, nullptr);
}

// round 4
// speedup vs baseline: 1.4826x; 1.1054x over previous
#include <cuda_runtime.h>
#include <math.h>
#include <stdint.h>

// ---------------------------------------------------------------------------
// Problem constants
// ---------------------------------------------------------------------------
#define NB    4
#define CDIM  128
#define HWP   4096           // 64*64
#define ROWS  (NB * HWP)     // 16384
#define NHEAD 4
#define DH    32
#define KS    7

// Scratch arena layout (floats)
#define OFF_XS    0u
#define OFF_XN    2097152u            // 16384*128
#define OFF_QKV   4194304u            // len 16384*384
#define OFF_T     11010048u           // len 16384*128
#define OFF_NA    13107200u
#define OFF_X2    15204352u
#define OFF_XN2   17301504u
#define OFF_H1    19398656u           // len 16384*512
#define OFF_GSUM  27787264u           // 512
#define OFF_G     27787776u           // 512
#define SCRATCH_FLOATS 27788288u

__device__ float d_scratch[SCRATCH_FLOATS];

__device__ __forceinline__ float gelu_exact(float x) {
    return 0.5f * x * (1.0f + erff(x * 0.7071067811865476f));
}

__device__ __forceinline__ uint32_t f2tf32(float f) {
    uint32_t r;
    asm("cvt.rna.tf32.f32 %0, %1;" : "=r"(r) : "f"(f));
    return r;
}

__device__ __forceinline__ void mma_tf32(float d[4], const uint32_t a[4], const uint32_t b[2]) {
    asm volatile(
        "mma.sync.aligned.m16n8k8.row.col.f32.tf32.tf32.f32 "
        "{%0,%1,%2,%3},{%4,%5,%6,%7},{%8,%9},{%0,%1,%2,%3};\n"
        : "+f"(d[0]), "+f"(d[1]), "+f"(d[2]), "+f"(d[3])
        : "r"(a[0]), "r"(a[1]), "r"(a[2]), "r"(a[3]), "r"(b[0]), "r"(b[1]));
}

// ---------------------------------------------------------------------------
// Kernel 1: NCHW -> NHWC transpose + LayerNorm1.  32 pixels per block.
// Block 0 additionally zeros the channel-attention accumulator.
// ---------------------------------------------------------------------------
__global__ __launch_bounds__(128)
void k_transpose_ln(const float* __restrict__ x,
                    const float* __restrict__ w, const float* __restrict__ b,
                    float* __restrict__ xs, float* __restrict__ xn,
                    float* __restrict__ gsum)
{
    __shared__ float s[32][129];
    __shared__ float smu[32], srs[32];
    int tid = threadIdx.x;
    if (blockIdx.x == 0) {
        #pragma unroll
        for (int i = 0; i < 4; i++) gsum[tid + i * 128] = 0.f;
    }
    int row0 = blockIdx.x * 32;
    int n  = row0 >> 12;
    int p0 = row0 & 4095;
    int pl = tid & 31;
    int cg = tid >> 5;       // 0..3

    #pragma unroll 4
    for (int it = 0; it < 32; it++) {
        int c = it * 4 + cg;
        s[pl][c] = x[((size_t)(n * CDIM + c) << 12) + p0 + pl];
    }
    __syncthreads();

    if (tid < 32) {
        float sum = 0.f, sq = 0.f;
        #pragma unroll 8
        for (int c = 0; c < CDIM; c++) { float v = s[tid][c]; sum += v; sq += v * v; }
        float mu  = sum * (1.0f / CDIM);
        float var = sq * (1.0f / CDIM) - mu * mu;
        smu[tid] = mu;
        srs[tid] = rsqrtf(var + 1e-5f);
    }
    __syncthreads();

    float wc = w[tid], bc = b[tid];
    #pragma unroll 4
    for (int it = 0; it < 32; it++) {
        float v = s[it][tid];
        size_t o = (size_t)(row0 + it) * CDIM + tid;
        xs[o] = v;
        xn[o] = (v - smu[it]) * srs[it] * wc + bc;
    }
}

// ---------------------------------------------------------------------------
// Pipelined tf32 GEMM: BM=64, BN=64, BK=32, 128 threads (2x2 warps).
// Register-prefetch of next K-tile overlaps global latency with MMA.
// ---------------------------------------------------------------------------
#define EPI_NONE 0
#define EPI_GELU 1
#define EPI_OUT  3   // out NCHW = acc+bias + e1(x2)

template<int EPI>
__device__ __forceinline__ void epi_write(float* __restrict__ C, int row, int col,
                                          int N, float v, const float* __restrict__ e1)
{
    if (EPI == EPI_GELU) {
        C[(size_t)row * N + col] = gelu_exact(v);
    } else if (EPI == EPI_NONE) {
        C[(size_t)row * N + col] = v;
    } else { // EPI_OUT: write NCHW
        v += e1[(size_t)row * CDIM + col];
        int bn = row >> 12, p = row & 4095;
        C[((size_t)(bn * CDIM + col) << 12) + p] = v;
    }
}

template<int EPI>
__global__ __launch_bounds__(128)
void k_mma(const float* __restrict__ A, const float* __restrict__ B,
           const float* __restrict__ bias, float* __restrict__ C,
           int M, int N, int K, const float* __restrict__ e1)
{
    constexpr int BM = 64, BN = 64, BK = 32;
    __shared__ uint32_t As[BM][BK + 4];
    __shared__ uint32_t Bs[BK][BN + 8];

    int tid  = threadIdx.x;
    int lane = tid & 31;
    int warp = tid >> 5;
    int wm = warp & 1, wn = warp >> 1;
    int m0 = blockIdx.y * BM, n0 = blockIdx.x * BN;
    int grp = lane >> 2, qk = lane & 3;

    float d[2][4][4];
    #pragma unroll
    for (int mt = 0; mt < 2; mt++)
        #pragma unroll
        for (int nt = 0; nt < 4; nt++)
            #pragma unroll
            for (int i = 0; i < 4; i++) d[mt][nt][i] = 0.f;

    int arow = tid >> 1, kseg = (tid & 1) * 16;
    int brow = tid >> 2, bcol = (tid & 3) * 16;

    float4 pa0, pa1, pa2, pa3, pb0, pb1, pb2, pb3;

#define LDG_TILE(k0) { \
    const float* ap = A + (size_t)(m0 + arow) * K + (k0) + kseg; \
    pa0 = *(const float4*)ap;       pa1 = *(const float4*)(ap + 4); \
    pa2 = *(const float4*)(ap + 8); pa3 = *(const float4*)(ap + 12); \
    const float* bp = B + (size_t)((k0) + brow) * N + n0 + bcol; \
    pb0 = *(const float4*)bp;       pb1 = *(const float4*)(bp + 4); \
    pb2 = *(const float4*)(bp + 8); pb3 = *(const float4*)(bp + 12); }

#define STS_TILE() { \
    As[arow][kseg+0]=f2tf32(pa0.x);  As[arow][kseg+1]=f2tf32(pa0.y);  As[arow][kseg+2]=f2tf32(pa0.z);  As[arow][kseg+3]=f2tf32(pa0.w); \
    As[arow][kseg+4]=f2tf32(pa1.x);  As[arow][kseg+5]=f2tf32(pa1.y);  As[arow][kseg+6]=f2tf32(pa1.z);  As[arow][kseg+7]=f2tf32(pa1.w); \
    As[arow][kseg+8]=f2tf32(pa2.x);  As[arow][kseg+9]=f2tf32(pa2.y);  As[arow][kseg+10]=f2tf32(pa2.z); As[arow][kseg+11]=f2tf32(pa2.w); \
    As[arow][kseg+12]=f2tf32(pa3.x); As[arow][kseg+13]=f2tf32(pa3.y); As[arow][kseg+14]=f2tf32(pa3.z); As[arow][kseg+15]=f2tf32(pa3.w); \
    Bs[brow][bcol+0]=f2tf32(pb0.x);  Bs[brow][bcol+1]=f2tf32(pb0.y);  Bs[brow][bcol+2]=f2tf32(pb0.z);  Bs[brow][bcol+3]=f2tf32(pb0.w); \
    Bs[brow][bcol+4]=f2tf32(pb1.x);  Bs[brow][bcol+5]=f2tf32(pb1.y);  Bs[brow][bcol+6]=f2tf32(pb1.z);  Bs[brow][bcol+7]=f2tf32(pb1.w); \
    Bs[brow][bcol+8]=f2tf32(pb2.x);  Bs[brow][bcol+9]=f2tf32(pb2.y);  Bs[brow][bcol+10]=f2tf32(pb2.z); Bs[brow][bcol+11]=f2tf32(pb2.w); \
    Bs[brow][bcol+12]=f2tf32(pb3.x); Bs[brow][bcol+13]=f2tf32(pb3.y); Bs[brow][bcol+14]=f2tf32(pb3.z); Bs[brow][bcol+15]=f2tf32(pb3.w); }

#define MMA_TILE() { \
    _Pragma("unroll") \
    for (int kk = 0; kk < BK; kk += 8) { \
        uint32_t af[2][4], bf[4][2]; \
        _Pragma("unroll") \
        for (int mt = 0; mt < 2; mt++) { \
            int r = wm * 32 + mt * 16 + grp; \
            af[mt][0] = As[r][kk + qk];     af[mt][1] = As[r + 8][kk + qk]; \
            af[mt][2] = As[r][kk + qk + 4]; af[mt][3] = As[r + 8][kk + qk + 4]; \
        } \
        _Pragma("unroll") \
        for (int nt = 0; nt < 4; nt++) { \
            int cidx = wn * 32 + nt * 8 + grp; \
            bf[nt][0] = Bs[kk + qk][cidx]; bf[nt][1] = Bs[kk + qk + 4][cidx]; \
        } \
        _Pragma("unroll") \
        for (int mt = 0; mt < 2; mt++) \
            _Pragma("unroll") \
            for (int nt = 0; nt < 4; nt++) \
                mma_tf32(d[mt][nt], af[mt], bf[nt]); \
    } }

    LDG_TILE(0);
    STS_TILE();
    __syncthreads();
    for (int k0 = BK; k0 < K; k0 += BK) {
        LDG_TILE(k0);
        MMA_TILE();
        __syncthreads();
        STS_TILE();
        __syncthreads();
    }
    MMA_TILE();

#undef LDG_TILE
#undef STS_TILE
#undef MMA_TILE

    #pragma unroll
    for (int mt = 0; mt < 2; mt++) {
        int rbase = m0 + wm * 32 + mt * 16 + grp;
        #pragma unroll
        for (int nt = 0; nt < 4; nt++) {
            int cbase = n0 + wn * 32 + nt * 8 + 2 * qk;
            float b0 = bias[cbase], b1 = bias[cbase + 1];
            epi_write<EPI>(C, rbase,     cbase,     N, d[mt][nt][0] + b0, e1);
            epi_write<EPI>(C, rbase,     cbase + 1, N, d[mt][nt][1] + b1, e1);
            epi_write<EPI>(C, rbase + 8, cbase,     N, d[mt][nt][2] + b0, e1);
            epi_write<EPI>(C, rbase + 8, cbase + 1, N, d[mt][nt][3] + b1, e1);
        }
    }
}

// ---------------------------------------------------------------------------
// Fused conv1 + GELU + conv2 + spatial-mean.  64 rows per block, 128 threads.
// t1 stays in smem; conv2_w fully cached in smem; column sums via shfl+atomic.
// ---------------------------------------------------------------------------
__global__ __launch_bounds__(128)
void k_conv(const float* __restrict__ xn,
            const float* __restrict__ w1, const float* __restrict__ b1,
            const float* __restrict__ w2, const float* __restrict__ b2,
            float* __restrict__ tout, float* __restrict__ gsum)
{
    __shared__ uint32_t As[64][36];
    __shared__ uint32_t Bs1[32][40];
    __shared__ uint32_t St1[64][36];
    __shared__ uint32_t Bs2[32][136];

    int tid  = threadIdx.x;
    int lane = tid & 31;
    int warp = tid >> 5;
    int grp = lane >> 2, qk = lane & 3;
    int m0 = blockIdx.x * 64;

    // cache conv2_w (32 x 128) in smem once
    {
        int r = tid >> 2, c0 = (tid & 3) * 32;
        #pragma unroll
        for (int i = 0; i < 8; i++) {
            float4 v = *(const float4*)(w2 + (size_t)r * 128 + c0 + i * 4);
            Bs2[r][c0 + i * 4 + 0] = f2tf32(v.x);
            Bs2[r][c0 + i * 4 + 1] = f2tf32(v.y);
            Bs2[r][c0 + i * 4 + 2] = f2tf32(v.z);
            Bs2[r][c0 + i * 4 + 3] = f2tf32(v.w);
        }
    }

    // ---- stage 1: t1 = xn @ w1 (64x32, K=128) ----
    float acc1[4][4];
    #pragma unroll
    for (int nt = 0; nt < 4; nt++)
        #pragma unroll
        for (int i = 0; i < 4; i++) acc1[nt][i] = 0.f;

    int arow = tid >> 1, kseg = (tid & 1) * 16;
    int b1row = tid >> 2, b1col = (tid & 3) * 8;

    for (int k0 = 0; k0 < 128; k0 += 32) {
        const float* ap = xn + (size_t)(m0 + arow) * CDIM + k0 + kseg;
        #pragma unroll
        for (int i = 0; i < 4; i++) {
            float4 v = *(const float4*)(ap + i * 4);
            As[arow][kseg + i * 4 + 0] = f2tf32(v.x);
            As[arow][kseg + i * 4 + 1] = f2tf32(v.y);
            As[arow][kseg + i * 4 + 2] = f2tf32(v.z);
            As[arow][kseg + i * 4 + 3] = f2tf32(v.w);
        }
        const float* bp = w1 + (size_t)(k0 + b1row) * 32 + b1col;
        #pragma unroll
        for (int i = 0; i < 2; i++) {
            float4 v = *(const float4*)(bp + i * 4);
            Bs1[b1row][b1col + i * 4 + 0] = f2tf32(v.x);
            Bs1[b1row][b1col + i * 4 + 1] = f2tf32(v.y);
            Bs1[b1row][b1col + i * 4 + 2] = f2tf32(v.z);
            Bs1[b1row][b1col + i * 4 + 3] = f2tf32(v.w);
        }
        __syncthreads();
        #pragma unroll
        for (int kk = 0; kk < 32; kk += 8) {
            uint32_t af[4], bf[4][2];
            int r = warp * 16 + grp;
            af[0] = As[r][kk + qk];     af[1] = As[r + 8][kk + qk];
            af[2] = As[r][kk + qk + 4]; af[3] = As[r + 8][kk + qk + 4];
            #pragma unroll
            for (int nt = 0; nt < 4; nt++) {
                bf[nt][0] = Bs1[kk + qk][nt * 8 + grp];
                bf[nt][1] = Bs1[kk + qk + 4][nt * 8 + grp];
            }
            #pragma unroll
            for (int nt = 0; nt < 4; nt++) mma_tf32(acc1[nt], af, bf[nt]);
        }
        __syncthreads();
    }

    // stage-1 epilogue: gelu -> St1 (tf32)
    {
        int r = warp * 16 + grp;
        #pragma unroll
        for (int nt = 0; nt < 4; nt++) {
            int c = nt * 8 + 2 * qk;
            float bb0 = b1[c], bb1 = b1[c + 1];
            St1[r][c]         = f2tf32(gelu_exact(acc1[nt][0] + bb0));
            St1[r][c + 1]     = f2tf32(gelu_exact(acc1[nt][1] + bb1));
            St1[r + 8][c]     = f2tf32(gelu_exact(acc1[nt][2] + bb0));
            St1[r + 8][c + 1] = f2tf32(gelu_exact(acc1[nt][3] + bb1));
        }
    }
    __syncthreads();

    // ---- stage 2: t = gelu(t1) @ w2 (64x128, K=32) ----
    float acc2[16][4];
    #pragma unroll
    for (int nt = 0; nt < 16; nt++)
        #pragma unroll
        for (int i = 0; i < 4; i++) acc2[nt][i] = 0.f;

    #pragma unroll
    for (int kk = 0; kk < 32; kk += 8) {
        uint32_t af[4];
        int r = warp * 16 + grp;
        af[0] = St1[r][kk + qk];     af[1] = St1[r + 8][kk + qk];
        af[2] = St1[r][kk + qk + 4]; af[3] = St1[r + 8][kk + qk + 4];
        #pragma unroll
        for (int nt = 0; nt < 16; nt++) {
            uint32_t bf[2];
            bf[0] = Bs2[kk + qk][nt * 8 + grp];
            bf[1] = Bs2[kk + qk + 4][nt * 8 + grp];
            mma_tf32(acc2[nt], af, bf);
        }
    }

    // stage-2 epilogue: write t, accumulate column sums into gsum
    int n = m0 >> 12;
    int r = warp * 16 + grp;
    #pragma unroll
    for (int nt = 0; nt < 16; nt++) {
        int c = nt * 8 + 2 * qk;
        float bb0 = b2[c], bb1 = b2[c + 1];
        float v0 = acc2[nt][0] + bb0, v1 = acc2[nt][1] + bb1;
        float v2 = acc2[nt][2] + bb0, v3 = acc2[nt][3] + bb1;
        size_t ro = (size_t)(m0 + r) * CDIM;
        tout[ro + c] = v0;             tout[ro + c + 1] = v1;
        tout[ro + 8 * CDIM + c] = v2;  tout[ro + 8 * CDIM + c + 1] = v3;
        float s0 = v0 + v2, s1 = v1 + v3;
        #pragma unroll
        for (int o = 4; o < 32; o <<= 1) {
            s0 += __shfl_xor_sync(0xffffffffu, s0, o);
            s1 += __shfl_xor_sync(0xffffffffu, s1, o);
        }
        if (lane < 4) {
            atomicAdd(&gsum[n * CDIM + c], s0);
            atomicAdd(&gsum[n * CDIM + c + 1], s1);
        }
    }
}

// ---------------------------------------------------------------------------
// Channel attention gates: one block per batch
// ---------------------------------------------------------------------------
__global__ __launch_bounds__(128)
void k_chatt(const float* __restrict__ gsum, float* __restrict__ g,
             const float* __restrict__ ca1w, const float* __restrict__ ca1b,
             const float* __restrict__ ca2w, const float* __restrict__ ca2b)
{
    __shared__ float gm[CDIM];
    __shared__ float r[7];
    int tid = threadIdx.x;
    int n = blockIdx.x;
    gm[tid] = gsum[n * CDIM + tid] * (1.0f / HWP);
    __syncthreads();
    if (tid < 7) {
        float s = ca1b[tid];
        for (int c = 0; c < CDIM; c++) s += gm[c] * ca1w[c * 7 + tid];
        r[tid] = fmaxf(s, 0.f);
    }
    __syncthreads();
    float s = ca2b[tid];
    #pragma unroll
    for (int jj = 0; jj < 7; jj++) s += r[jj] * ca2w[jj * CDIM + tid];
    g[n * CDIM + tid] = 1.0f / (1.0f + expf(-s));
}

// ---------------------------------------------------------------------------
// Neighborhood attention, smem-tiled.
// Block = (8x8 pixel tile, batch, head). 256 threads = 8 warps; warp = 8 pixels.
// ---------------------------------------------------------------------------
__global__ __launch_bounds__(256)
void k_na(const float* __restrict__ qkv, const float* __restrict__ rpb,
          float* __restrict__ na)
{
    __shared__ float skv[196][32];   // 14x14 window, 32 channels
    __shared__ float ssc[64][50];    // per-pixel scores (49, padded)
    __shared__ float srpb[169];

    int tid  = threadIdx.x;
    int lane = tid & 31;
    int warp = tid >> 5;

    int n = blockIdx.y >> 2;
    int h = blockIdx.y & 3;
    int ti = blockIdx.x >> 3, tj = blockIdx.x & 7;
    int i0 = ti * 8, j0 = tj * 8;
    int wi0 = i0 - 3; wi0 = wi0 < 0 ? 0 : (wi0 > 57 ? 57 : wi0);
    int wj0 = j0 - 3; wj0 = wj0 < 0 ? 0 : (wj0 > 57 ? 57 : wj0);

    if (tid < 169) srpb[tid] = rpb[h * 169 + tid];

    const float* qkv_base = qkv + (size_t)(n * HWP) * 384 + h * DH;

    // ---- phase 1: load K window ----
    #pragma unroll
    for (int idx = tid; idx < 196 * 32; idx += 256) {
        int r = idx >> 5, c = idx & 31;
        int gi = wi0 + r / 14; gi = gi > 63 ? 63 : gi;
        int gj = wj0 + r % 14; gj = gj > 63 ? 63 : gj;
        skv[r][c] = qkv_base[(size_t)(gi * 64 + gj) * 384 + 128 + c];
    }
    __syncthreads();

    // ---- phase 2: scores ----
    int pix0 = warp * 8;
    #pragma unroll
    for (int pp = 0; pp < 8; pp++) {
        int p = pix0 + pp;
        int i = i0 + (p >> 3), j = j0 + (p & 7);
        int ni = i - 3; ni = ni < 0 ? 0 : (ni > 57 ? 57 : ni);
        int nj = j - 3; nj = nj < 0 ? 0 : (nj > 57 ? 57 : nj);
        float q = qkv_base[(size_t)(i * 64 + j) * 384 + lane] * 0.17677669529663687f;
        int nbase = (ni - wi0) * 14 + (nj - wj0);
        int bbase = (ni - i + 6) * 13 + (nj - j + 6);
        #pragma unroll
        for (int a = 0; a < KS; a++) {
            #pragma unroll
            for (int bcol = 0; bcol < KS; bcol++) {
                float s = q * skv[nbase + a * 14 + bcol][lane];
                #pragma unroll
                for (int o = 16; o > 0; o >>= 1) s += __shfl_xor_sync(0xffffffffu, s, o);
                if (lane == 0)
                    ssc[p][a * KS + bcol] = s + srpb[bbase + a * 13 + bcol];
            }
        }
    }
    __syncthreads();

    // ---- phase 3: overwrite window with V ----
    #pragma unroll
    for (int idx = tid; idx < 196 * 32; idx += 256) {
        int r = idx >> 5, c = idx & 31;
        int gi = wi0 + r / 14; gi = gi > 63 ? 63 : gi;
        int gj = wj0 + r % 14; gj = gj > 63 ? 63 : gj;
        skv[r][c] = qkv_base[(size_t)(gi * 64 + gj) * 384 + 256 + c];
    }
    __syncthreads();

    // ---- phase 4: softmax + V accumulate ----
    #pragma unroll
    for (int pp = 0; pp < 8; pp++) {
        int p = pix0 + pp;
        int i = i0 + (p >> 3), j = j0 + (p & 7);
        int ni = i - 3; ni = ni < 0 ? 0 : (ni > 57 ? 57 : ni);
        int nj = j - 3; nj = nj < 0 ? 0 : (nj > 57 ? 57 : nj);
        int nbase = (ni - wi0) * 14 + (nj - wj0);

        float a0 = ssc[p][lane];
        float a1 = (lane < 17) ? ssc[p][lane + 32] : -1e30f;
        float m = fmaxf(a0, a1);
        #pragma unroll
        for (int o = 16; o > 0; o >>= 1) m = fmaxf(m, __shfl_xor_sync(0xffffffffu, m, o));
        float e0 = __expf(a0 - m);
        float e1 = (lane < 17) ? __expf(a1 - m) : 0.f;
        float ps = e0 + e1;
        #pragma unroll
        for (int o = 16; o > 0; o >>= 1) ps += __shfl_xor_sync(0xffffffffu, ps, o);
        float inv = 1.0f / ps;
        ssc[p][lane] = e0 * inv;
        if (lane < 17) ssc[p][lane + 32] = e1 * inv;
        __syncwarp();

        float out = 0.f;
        #pragma unroll
        for (int a = 0; a < KS; a++) {
            #pragma unroll
            for (int bcol = 0; bcol < KS; bcol++) {
                out = fmaf(ssc[p][a * KS + bcol], skv[nbase + a * 14 + bcol][lane], out);
            }
        }
        na[(size_t)(n * HWP + i * 64 + j) * CDIM + h * DH + lane] = out;
    }
}

// ---------------------------------------------------------------------------
// Fused proj GEMM + residual combine + LayerNorm2.
// BM=64, BN=128 (full rows), K=128, 128 threads = 4 warps (16 rows each).
// ---------------------------------------------------------------------------
__global__ __launch_bounds__(128)
void k_proj_ln(const float* __restrict__ A /*na*/, const float* __restrict__ B /*proj_w*/,
               const float* __restrict__ bias,
               const float* __restrict__ xs, const float* __restrict__ t,
               const float* __restrict__ g,
               const float* __restrict__ w2, const float* __restrict__ b2,
               float* __restrict__ x2, float* __restrict__ xn2)
{
    __shared__ union SU {
        struct { uint32_t As[64][36]; uint32_t Bs[32][136]; } gm;
        float x2s[64][132];
    } sm;

    int tid  = threadIdx.x;
    int lane = tid & 31;
    int warp = tid >> 5;
    int grp = lane >> 2, qk = lane & 3;
    int m0 = blockIdx.x * 64;
    int n = m0 >> 12;

    float acc[16][4];
    #pragma unroll
    for (int nt = 0; nt < 16; nt++)
        #pragma unroll
        for (int i = 0; i < 4; i++) acc[nt][i] = 0.f;

    int arow = tid >> 1, kseg = (tid & 1) * 16;
    int brow = tid >> 2, bcol = (tid & 3) * 32;

    for (int k0 = 0; k0 < 128; k0 += 32) {
        const float* ap = A + (size_t)(m0 + arow) * CDIM + k0 + kseg;
        #pragma unroll
        for (int i = 0; i < 4; i++) {
            float4 v = *(const float4*)(ap + i * 4);
            sm.gm.As[arow][kseg + i * 4 + 0] = f2tf32(v.x);
            sm.gm.As[arow][kseg + i * 4 + 1] = f2tf32(v.y);
            sm.gm.As[arow][kseg + i * 4 + 2] = f2tf32(v.z);
            sm.gm.As[arow][kseg + i * 4 + 3] = f2tf32(v.w);
        }
        const float* bp = B + (size_t)(k0 + brow) * CDIM + bcol;
        #pragma unroll
        for (int i = 0; i < 8; i++) {
            float4 v = *(const float4*)(bp + i * 4);
            sm.gm.Bs[brow][bcol + i * 4 + 0] = f2tf32(v.x);
            sm.gm.Bs[brow][bcol + i * 4 + 1] = f2tf32(v.y);
            sm.gm.Bs[brow][bcol + i * 4 + 2] = f2tf32(v.z);
            sm.gm.Bs[brow][bcol + i * 4 + 3] = f2tf32(v.w);
        }
        __syncthreads();
        #pragma unroll
        for (int kk = 0; kk < 32; kk += 8) {
            uint32_t af[4];
            int r = warp * 16 + grp;
            af[0] = sm.gm.As[r][kk + qk];     af[1] = sm.gm.As[r + 8][kk + qk];
            af[2] = sm.gm.As[r][kk + qk + 4]; af[3] = sm.gm.As[r + 8][kk + qk + 4];
            #pragma unroll
            for (int nt = 0; nt < 16; nt++) {
                uint32_t bf[2];
                bf[0] = sm.gm.Bs[kk + qk][nt * 8 + grp];
                bf[1] = sm.gm.Bs[kk + qk + 4][nt * 8 + grp];
                mma_tf32(acc[nt], af, bf);
            }
        }
        __syncthreads();
    }

    // epilogue: x2 value = acc + bias + xs + t*g*0.02 -> smem
    {
        int r = warp * 16 + grp;
        size_t ro0 = (size_t)(m0 + r) * CDIM;
        size_t ro1 = (size_t)(m0 + r + 8) * CDIM;
        #pragma unroll
        for (int nt = 0; nt < 16; nt++) {
            int c = nt * 8 + 2 * qk;
            float bb0 = bias[c], bb1 = bias[c + 1];
            float g0 = g[n * CDIM + c] * 0.02f, g1 = g[n * CDIM + c + 1] * 0.02f;
            sm.x2s[r][c]         = acc[nt][0] + bb0 + xs[ro0 + c]     + t[ro0 + c]     * g0;
            sm.x2s[r][c + 1]     = acc[nt][1] + bb1 + xs[ro0 + c + 1] + t[ro0 + c + 1] * g1;
            sm.x2s[r + 8][c]     = acc[nt][2] + bb0 + xs[ro1 + c]     + t[ro1 + c]     * g0;
            sm.x2s[r + 8][c + 1] = acc[nt][3] + bb1 + xs[ro1 + c + 1] + t[ro1 + c + 1] * g1;
        }
    }
    __syncthreads();

    // LayerNorm over each row, write x2 and xn2
    float w2r[4], b2r[4];
    #pragma unroll
    for (int k = 0; k < 4; k++) { w2r[k] = w2[lane + 32 * k]; b2r[k] = b2[lane + 32 * k]; }

    #pragma unroll
    for (int rr = 0; rr < 16; rr++) {
        int r = warp * 16 + rr;
        float v[4];
        float sum = 0.f, sq = 0.f;
        #pragma unroll
        for (int k = 0; k < 4; k++) {
            v[k] = sm.x2s[r][lane + 32 * k];
            sum += v[k]; sq += v[k] * v[k];
        }
        #pragma unroll
        for (int o = 16; o > 0; o >>= 1) {
            sum += __shfl_xor_sync(0xffffffffu, sum, o);
            sq  += __shfl_xor_sync(0xffffffffu, sq, o);
        }
        float mu = sum * (1.0f / CDIM);
        float rs = rsqrtf(sq * (1.0f / CDIM) - mu * mu + 1e-5f);
        size_t ro = (size_t)(m0 + r) * CDIM;
        #pragma unroll
        for (int k = 0; k < 4; k++) {
            x2[ro + lane + 32 * k]  = v[k];
            xn2[ro + lane + 32 * k] = (v[k] - mu) * rs * w2r[k] + b2r[k];
        }
    }
}

// ---------------------------------------------------------------------------
// Launch
// ---------------------------------------------------------------------------
extern "C" void kernel_launch(void* const* d_in, const int* in_sizes, int n_in,
                              void* d_out, int out_size)
{
    const float* x      = (const float*)d_in[0];
    const float* ln1_w  = (const float*)d_in[1];
    const float* ln1_b  = (const float*)d_in[2];
    const float* ln2_w  = (const float*)d_in[3];
    const float* ln2_b  = (const float*)d_in[4];
    const float* qkv_w  = (const float*)d_in[5];
    const float* qkv_b  = (const float*)d_in[6];
    const float* proj_w = (const float*)d_in[7];
    const float* proj_b = (const float*)d_in[8];
    const float* rpb    = (const float*)d_in[9];
    const float* conv1_w= (const float*)d_in[10];
    const float* conv1_b= (const float*)d_in[11];
    const float* conv2_w= (const float*)d_in[12];
    const float* conv2_b= (const float*)d_in[13];
    const float* ca1_w  = (const float*)d_in[14];
    const float* ca1_b  = (const float*)d_in[15];
    const float* ca2_w  = (const float*)d_in[16];
    const float* ca2_b  = (const float*)d_in[17];
    const float* fc1_w  = (const float*)d_in[18];
    const float* fc1_b  = (const float*)d_in[19];
    const float* fc2_w  = (const float*)d_in[20];
    const float* fc2_b  = (const float*)d_in[21];
    float* out = (float*)d_out;

    float* scr = nullptr;
    cudaGetSymbolAddress((void**)&scr, d_scratch);
    float* xs   = scr + OFF_XS;
    float* xn   = scr + OFF_XN;
    float* qkv  = scr + OFF_QKV;
    float* t    = scr + OFF_T;
    float* na   = scr + OFF_NA;
    float* x2   = scr + OFF_X2;
    float* xn2  = scr + OFF_XN2;
    float* h1   = scr + OFF_H1;
    float* gsum = scr + OFF_GSUM;
    float* g    = scr + OFF_G;

    // 1. transpose + LN1 (+ zero gsum)
    k_transpose_ln<<<ROWS / 32, 128>>>(x, ln1_w, ln1_b, xs, xn, gsum);
    // 2. qkv GEMM: 16384 x 384 x 128
    k_mma<EPI_NONE><<<dim3(6, ROWS / 64), 128>>>(xn, qkv_w, qkv_b, qkv,
                                                 ROWS, 384, 128, nullptr);
    // 3. fused conv1+gelu+conv2+colsum
    k_conv<<<ROWS / 64, 128>>>(xn, conv1_w, conv1_b, conv2_w, conv2_b, t, gsum);
    // 4. channel attention gates
    k_chatt<<<NB, 128>>>(gsum, g, ca1_w, ca1_b, ca2_w, ca2_b);
    // 5. neighborhood attention (tiled)
    k_na<<<dim3(64, NB * NHEAD), 256>>>(qkv, rpb, na);
    // 6. fused proj + residual + LN2
    k_proj_ln<<<ROWS / 64, 128>>>(na, proj_w, proj_b, xs, t, g,
                                  ln2_w, ln2_b, x2, xn2);
    // 7. fc1 + gelu: 16384 x 512 x 128
    k_mma<EPI_GELU><<<dim3(8, ROWS / 64), 128>>>(xn2, fc1_w, fc1_b, h1,
                                                 ROWS, 512, 128, nullptr);
    // 8. fc2 + residual, write NCHW output
    k_mma<EPI_OUT><<<dim3(2, ROWS / 64), 128>>>(h1, fc2_w, fc2_b, out,
                                                ROWS, 128, 512, x2);
}

// round 5
// speedup vs baseline: 2.0274x; 1.3675x over previous
#include <cuda_runtime.h>
#include <math.h>
#include <stdint.h>

// ---------------------------------------------------------------------------
// Problem constants
// ---------------------------------------------------------------------------
#define NB    4
#define CDIM  128
#define HWP   4096           // 64*64
#define ROWS  (NB * HWP)     // 16384
#define NHEAD 4
#define DH    32
#define KS    7

// Scratch arena layout (floats)
#define OFF_XS    0u
#define OFF_XN    2097152u            // 16384*128
#define OFF_QKV   4194304u            // len 16384*384
#define OFF_T     11010048u           // len 16384*128
#define OFF_NA    13107200u
#define OFF_X2    15204352u
#define OFF_XN2   17301504u
#define OFF_H1    19398656u           // len 16384*512
#define OFF_GSUM  27787264u           // 512
#define SCRATCH_FLOATS 27788288u

__device__ float d_scratch[SCRATCH_FLOATS];

__device__ __forceinline__ float gelu_exact(float x) {
    return 0.5f * x * (1.0f + erff(x * 0.7071067811865476f));
}

__device__ __forceinline__ uint32_t f2tf32(float f) {
    uint32_t r;
    asm("cvt.rna.tf32.f32 %0, %1;" : "=r"(r) : "f"(f));
    return r;
}

__device__ __forceinline__ void mma_tf32(float d[4], const uint32_t a[4], const uint32_t b[2]) {
    asm volatile(
        "mma.sync.aligned.m16n8k8.row.col.f32.tf32.tf32.f32 "
        "{%0,%1,%2,%3},{%4,%5,%6,%7},{%8,%9},{%0,%1,%2,%3};\n"
        : "+f"(d[0]), "+f"(d[1]), "+f"(d[2]), "+f"(d[3])
        : "r"(a[0]), "r"(a[1]), "r"(a[2]), "r"(a[3]), "r"(b[0]), "r"(b[1]));
}

// ---------------------------------------------------------------------------
// Kernel 1: NCHW -> NHWC transpose + LayerNorm1.  32 pixels per block.
// Block 0 additionally zeros the channel-attention accumulator.
// ---------------------------------------------------------------------------
__global__ __launch_bounds__(128)
void k_transpose_ln(const float* __restrict__ x,
                    const float* __restrict__ w, const float* __restrict__ b,
                    float* __restrict__ xs, float* __restrict__ xn,
                    float* __restrict__ gsum)
{
    __shared__ float s[32][129];
    __shared__ float smu[32], srs[32];
    int tid = threadIdx.x;
    if (blockIdx.x == 0) {
        #pragma unroll
        for (int i = 0; i < 4; i++) gsum[tid + i * 128] = 0.f;
    }
    int row0 = blockIdx.x * 32;
    int n  = row0 >> 12;
    int p0 = row0 & 4095;
    int pl = tid & 31;
    int cg = tid >> 5;       // 0..3

    #pragma unroll 4
    for (int it = 0; it < 32; it++) {
        int c = it * 4 + cg;
        s[pl][c] = x[((size_t)(n * CDIM + c) << 12) + p0 + pl];
    }
    __syncthreads();

    if (tid < 32) {
        float sum = 0.f, sq = 0.f;
        #pragma unroll 8
        for (int c = 0; c < CDIM; c++) { float v = s[tid][c]; sum += v; sq += v * v; }
        float mu  = sum * (1.0f / CDIM);
        float var = sq * (1.0f / CDIM) - mu * mu;
        smu[tid] = mu;
        srs[tid] = rsqrtf(var + 1e-5f);
    }
    __syncthreads();

    float wc = w[tid], bc = b[tid];
    #pragma unroll 4
    for (int it = 0; it < 32; it++) {
        float v = s[it][tid];
        size_t o = (size_t)(row0 + it) * CDIM + tid;
        xs[o] = v;
        xn[o] = (v - smu[it]) * srs[it] * wc + bc;
    }
}

// ---------------------------------------------------------------------------
// Pipelined tf32 GEMM: BM=64, BN=64, BK=32, 128 threads (2x2 warps).
// ---------------------------------------------------------------------------
#define EPI_NONE 0
#define EPI_GELU 1
#define EPI_OUT  3   // out NCHW = acc+bias + e1(x2)

template<int EPI>
__device__ __forceinline__ void epi_write(float* __restrict__ C, int row, int col,
                                          int N, float v, const float* __restrict__ e1)
{
    if (EPI == EPI_GELU) {
        C[(size_t)row * N + col] = gelu_exact(v);
    } else if (EPI == EPI_NONE) {
        C[(size_t)row * N + col] = v;
    } else { // EPI_OUT: write NCHW
        v += e1[(size_t)row * CDIM + col];
        int bn = row >> 12, p = row & 4095;
        C[((size_t)(bn * CDIM + col) << 12) + p] = v;
    }
}

template<int EPI>
__global__ __launch_bounds__(128)
void k_mma(const float* __restrict__ A, const float* __restrict__ B,
           const float* __restrict__ bias, float* __restrict__ C,
           int M, int N, int K, const float* __restrict__ e1)
{
    constexpr int BM = 64, BN = 64, BK = 32;
    __shared__ uint32_t As[BM][BK + 4];
    __shared__ uint32_t Bs[BK][BN + 8];

    int tid  = threadIdx.x;
    int lane = tid & 31;
    int warp = tid >> 5;
    int wm = warp & 1, wn = warp >> 1;
    int m0 = blockIdx.y * BM, n0 = blockIdx.x * BN;
    int grp = lane >> 2, qk = lane & 3;

    float d[2][4][4];
    #pragma unroll
    for (int mt = 0; mt < 2; mt++)
        #pragma unroll
        for (int nt = 0; nt < 4; nt++)
            #pragma unroll
            for (int i = 0; i < 4; i++) d[mt][nt][i] = 0.f;

    int arow = tid >> 1, kseg = (tid & 1) * 16;
    int brow = tid >> 2, bcol = (tid & 3) * 16;

    float4 pa0, pa1, pa2, pa3, pb0, pb1, pb2, pb3;

#define LDG_TILE(k0) { \
    const float* ap = A + (size_t)(m0 + arow) * K + (k0) + kseg; \
    pa0 = *(const float4*)ap;       pa1 = *(const float4*)(ap + 4); \
    pa2 = *(const float4*)(ap + 8); pa3 = *(const float4*)(ap + 12); \
    const float* bp = B + (size_t)((k0) + brow) * N + n0 + bcol; \
    pb0 = *(const float4*)bp;       pb1 = *(const float4*)(bp + 4); \
    pb2 = *(const float4*)(bp + 8); pb3 = *(const float4*)(bp + 12); }

#define STS_TILE() { \
    As[arow][kseg+0]=f2tf32(pa0.x);  As[arow][kseg+1]=f2tf32(pa0.y);  As[arow][kseg+2]=f2tf32(pa0.z);  As[arow][kseg+3]=f2tf32(pa0.w); \
    As[arow][kseg+4]=f2tf32(pa1.x);  As[arow][kseg+5]=f2tf32(pa1.y);  As[arow][kseg+6]=f2tf32(pa1.z);  As[arow][kseg+7]=f2tf32(pa1.w); \
    As[arow][kseg+8]=f2tf32(pa2.x);  As[arow][kseg+9]=f2tf32(pa2.y);  As[arow][kseg+10]=f2tf32(pa2.z); As[arow][kseg+11]=f2tf32(pa2.w); \
    As[arow][kseg+12]=f2tf32(pa3.x); As[arow][kseg+13]=f2tf32(pa3.y); As[arow][kseg+14]=f2tf32(pa3.z); As[arow][kseg+15]=f2tf32(pa3.w); \
    Bs[brow][bcol+0]=f2tf32(pb0.x);  Bs[brow][bcol+1]=f2tf32(pb0.y);  Bs[brow][bcol+2]=f2tf32(pb0.z);  Bs[brow][bcol+3]=f2tf32(pb0.w); \
    Bs[brow][bcol+4]=f2tf32(pb1.x);  Bs[brow][bcol+5]=f2tf32(pb1.y);  Bs[brow][bcol+6]=f2tf32(pb1.z);  Bs[brow][bcol+7]=f2tf32(pb1.w); \
    Bs[brow][bcol+8]=f2tf32(pb2.x);  Bs[brow][bcol+9]=f2tf32(pb2.y);  Bs[brow][bcol+10]=f2tf32(pb2.z); Bs[brow][bcol+11]=f2tf32(pb2.w); \
    Bs[brow][bcol+12]=f2tf32(pb3.x); Bs[brow][bcol+13]=f2tf32(pb3.y); Bs[brow][bcol+14]=f2tf32(pb3.z); Bs[brow][bcol+15]=f2tf32(pb3.w); }

#define MMA_TILE() { \
    _Pragma("unroll") \
    for (int kk = 0; kk < BK; kk += 8) { \
        uint32_t af[2][4], bf[4][2]; \
        _Pragma("unroll") \
        for (int mt = 0; mt < 2; mt++) { \
            int r = wm * 32 + mt * 16 + grp; \
            af[mt][0] = As[r][kk + qk];     af[mt][1] = As[r + 8][kk + qk]; \
            af[mt][2] = As[r][kk + qk + 4]; af[mt][3] = As[r + 8][kk + qk + 4]; \
        } \
        _Pragma("unroll") \
        for (int nt = 0; nt < 4; nt++) { \
            int cidx = wn * 32 + nt * 8 + grp; \
            bf[nt][0] = Bs[kk + qk][cidx]; bf[nt][1] = Bs[kk + qk + 4][cidx]; \
        } \
        _Pragma("unroll") \
        for (int mt = 0; mt < 2; mt++) \
            _Pragma("unroll") \
            for (int nt = 0; nt < 4; nt++) \
                mma_tf32(d[mt][nt], af[mt], bf[nt]); \
    } }

    LDG_TILE(0);
    STS_TILE();
    __syncthreads();
    for (int k0 = BK; k0 < K; k0 += BK) {
        LDG_TILE(k0);
        MMA_TILE();
        __syncthreads();
        STS_TILE();
        __syncthreads();
    }
    MMA_TILE();

#undef LDG_TILE
#undef STS_TILE
#undef MMA_TILE

    #pragma unroll
    for (int mt = 0; mt < 2; mt++) {
        int rbase = m0 + wm * 32 + mt * 16 + grp;
        #pragma unroll
        for (int nt = 0; nt < 4; nt++) {
            int cbase = n0 + wn * 32 + nt * 8 + 2 * qk;
            float b0 = bias[cbase], b1 = bias[cbase + 1];
            epi_write<EPI>(C, rbase,     cbase,     N, d[mt][nt][0] + b0, e1);
            epi_write<EPI>(C, rbase,     cbase + 1, N, d[mt][nt][1] + b1, e1);
            epi_write<EPI>(C, rbase + 8, cbase,     N, d[mt][nt][2] + b0, e1);
            epi_write<EPI>(C, rbase + 8, cbase + 1, N, d[mt][nt][3] + b1, e1);
        }
    }
}

// ---------------------------------------------------------------------------
// Fused conv1 + GELU + conv2 + spatial-mean.  64 rows per block, 128 threads.
// ---------------------------------------------------------------------------
__global__ __launch_bounds__(128)
void k_conv(const float* __restrict__ xn,
            const float* __restrict__ w1, const float* __restrict__ b1,
            const float* __restrict__ w2, const float* __restrict__ b2,
            float* __restrict__ tout, float* __restrict__ gsum)
{
    __shared__ uint32_t As[64][36];
    __shared__ uint32_t Bs1[32][40];
    __shared__ uint32_t St1[64][36];
    __shared__ uint32_t Bs2[32][136];

    int tid  = threadIdx.x;
    int lane = tid & 31;
    int warp = tid >> 5;
    int grp = lane >> 2, qk = lane & 3;
    int m0 = blockIdx.x * 64;

    // cache conv2_w (32 x 128) in smem once
    {
        int r = tid >> 2, c0 = (tid & 3) * 32;
        #pragma unroll
        for (int i = 0; i < 8; i++) {
            float4 v = *(const float4*)(w2 + (size_t)r * 128 + c0 + i * 4);
            Bs2[r][c0 + i * 4 + 0] = f2tf32(v.x);
            Bs2[r][c0 + i * 4 + 1] = f2tf32(v.y);
            Bs2[r][c0 + i * 4 + 2] = f2tf32(v.z);
            Bs2[r][c0 + i * 4 + 3] = f2tf32(v.w);
        }
    }

    float acc1[4][4];
    #pragma unroll
    for (int nt = 0; nt < 4; nt++)
        #pragma unroll
        for (int i = 0; i < 4; i++) acc1[nt][i] = 0.f;

    int arow = tid >> 1, kseg = (tid & 1) * 16;
    int b1row = tid >> 2, b1col = (tid & 3) * 8;

    for (int k0 = 0; k0 < 128; k0 += 32) {
        const float* ap = xn + (size_t)(m0 + arow) * CDIM + k0 + kseg;
        #pragma unroll
        for (int i = 0; i < 4; i++) {
            float4 v = *(const float4*)(ap + i * 4);
            As[arow][kseg + i * 4 + 0] = f2tf32(v.x);
            As[arow][kseg + i * 4 + 1] = f2tf32(v.y);
            As[arow][kseg + i * 4 + 2] = f2tf32(v.z);
            As[arow][kseg + i * 4 + 3] = f2tf32(v.w);
        }
        const float* bp = w1 + (size_t)(k0 + b1row) * 32 + b1col;
        #pragma unroll
        for (int i = 0; i < 2; i++) {
            float4 v = *(const float4*)(bp + i * 4);
            Bs1[b1row][b1col + i * 4 + 0] = f2tf32(v.x);
            Bs1[b1row][b1col + i * 4 + 1] = f2tf32(v.y);
            Bs1[b1row][b1col + i * 4 + 2] = f2tf32(v.z);
            Bs1[b1row][b1col + i * 4 + 3] = f2tf32(v.w);
        }
        __syncthreads();
        #pragma unroll
        for (int kk = 0; kk < 32; kk += 8) {
            uint32_t af[4], bf[4][2];
            int r = warp * 16 + grp;
            af[0] = As[r][kk + qk];     af[1] = As[r + 8][kk + qk];
            af[2] = As[r][kk + qk + 4]; af[3] = As[r + 8][kk + qk + 4];
            #pragma unroll
            for (int nt = 0; nt < 4; nt++) {
                bf[nt][0] = Bs1[kk + qk][nt * 8 + grp];
                bf[nt][1] = Bs1[kk + qk + 4][nt * 8 + grp];
            }
            #pragma unroll
            for (int nt = 0; nt < 4; nt++) mma_tf32(acc1[nt], af, bf[nt]);
        }
        __syncthreads();
    }

    {
        int r = warp * 16 + grp;
        #pragma unroll
        for (int nt = 0; nt < 4; nt++) {
            int c = nt * 8 + 2 * qk;
            float bb0 = b1[c], bb1 = b1[c + 1];
            St1[r][c]         = f2tf32(gelu_exact(acc1[nt][0] + bb0));
            St1[r][c + 1]     = f2tf32(gelu_exact(acc1[nt][1] + bb1));
            St1[r + 8][c]     = f2tf32(gelu_exact(acc1[nt][2] + bb0));
            St1[r + 8][c + 1] = f2tf32(gelu_exact(acc1[nt][3] + bb1));
        }
    }
    __syncthreads();

    float acc2[16][4];
    #pragma unroll
    for (int nt = 0; nt < 16; nt++)
        #pragma unroll
        for (int i = 0; i < 4; i++) acc2[nt][i] = 0.f;

    #pragma unroll
    for (int kk = 0; kk < 32; kk += 8) {
        uint32_t af[4];
        int r = warp * 16 + grp;
        af[0] = St1[r][kk + qk];     af[1] = St1[r + 8][kk + qk];
        af[2] = St1[r][kk + qk + 4]; af[3] = St1[r + 8][kk + qk + 4];
        #pragma unroll
        for (int nt = 0; nt < 16; nt++) {
            uint32_t bf[2];
            bf[0] = Bs2[kk + qk][nt * 8 + grp];
            bf[1] = Bs2[kk + qk + 4][nt * 8 + grp];
            mma_tf32(acc2[nt], af, bf);
        }
    }

    int n = m0 >> 12;
    int r = warp * 16 + grp;
    #pragma unroll
    for (int nt = 0; nt < 16; nt++) {
        int c = nt * 8 + 2 * qk;
        float bb0 = b2[c], bb1 = b2[c + 1];
        float v0 = acc2[nt][0] + bb0, v1 = acc2[nt][1] + bb1;
        float v2 = acc2[nt][2] + bb0, v3 = acc2[nt][3] + bb1;
        size_t ro = (size_t)(m0 + r) * CDIM;
        tout[ro + c] = v0;             tout[ro + c + 1] = v1;
        tout[ro + 8 * CDIM + c] = v2;  tout[ro + 8 * CDIM + c + 1] = v3;
        float s0 = v0 + v2, s1 = v1 + v3;
        #pragma unroll
        for (int o = 4; o < 32; o <<= 1) {
            s0 += __shfl_xor_sync(0xffffffffu, s0, o);
            s1 += __shfl_xor_sync(0xffffffffu, s1, o);
        }
        if (lane < 4) {
            atomicAdd(&gsum[n * CDIM + c], s0);
            atomicAdd(&gsum[n * CDIM + c + 1], s1);
        }
    }
}

// ---------------------------------------------------------------------------
// Neighborhood attention via tensor-core scores.
// Block = (8x8 pixel tile, batch, head). 256 threads = 8 warps.
// S = Q(64x32) @ Kwin(196x32)^T via tf32 MMA; scatter valid 49/pixel (+rpb);
// softmax + FMA AV.
// ---------------------------------------------------------------------------
__global__ __launch_bounds__(256)
void k_na(const float* __restrict__ qkv, const float* __restrict__ rpb,
          float* __restrict__ na)
{
    __shared__ union U {
        struct { uint32_t Qs[64][36]; uint32_t Ks[32][200]; } s1;
        float Vs[196][32];
    } su;
    __shared__ float ssc[64][50];
    __shared__ float srpb[169];

    int tid  = threadIdx.x;
    int lane = tid & 31;
    int warp = tid >> 5;
    int grp = lane >> 2, qk = lane & 3;

    int n = blockIdx.y >> 2;
    int h = blockIdx.y & 3;
    int i0 = (blockIdx.x >> 3) * 8, j0 = (blockIdx.x & 7) * 8;
    int wi0 = i0 - 3; wi0 = wi0 < 0 ? 0 : wi0;
    int wj0 = j0 - 3; wj0 = wj0 < 0 ? 0 : wj0;

    if (tid < 169) srpb[tid] = rpb[h * 169 + tid];

    const float* qb = qkv + (size_t)(n * HWP) * 384 + h * DH;

    // ---- load Q (scaled, tf32) and K window (transposed, tf32) ----
    #pragma unroll
    for (int idx = tid; idx < 64 * 32; idx += 256) {
        int p = idx >> 5, c = idx & 31;
        int i = i0 + (p >> 3), j = j0 + (p & 7);
        su.s1.Qs[p][c] = f2tf32(qb[(size_t)(i * 64 + j) * 384 + c] * 0.17677669529663687f);
    }
    #pragma unroll
    for (int idx = tid; idx < 196 * 32; idx += 256) {
        int widx = idx >> 5, c = idx & 31;
        int rw = (widx * 2341) >> 15;
        int cw = widx - rw * 14;
        int gi = wi0 + rw; gi = gi > 63 ? 63 : gi;
        int gj = wj0 + cw; gj = gj > 63 ? 63 : gj;
        su.s1.Ks[c][widx] = f2tf32(qb[(size_t)(gi * 64 + gj) * 384 + 128 + c]);
    }
    __syncthreads();

    // ---- scores MMA: warp (mt = warp>>1 rows, nh = warp&1 col half) ----
    int mt = warp >> 1;
    int nh = warp & 1;
    int gt0 = nh ? 12 : 0;
    int gt1 = nh ? 25 : 12;

    float sacc[13][4];
    #pragma unroll
    for (int t = 0; t < 13; t++)
        #pragma unroll
        for (int i = 0; i < 4; i++) sacc[t][i] = 0.f;

    #pragma unroll
    for (int kk = 0; kk < 32; kk += 8) {
        uint32_t af[4];
        int r = mt * 16 + grp;
        af[0] = su.s1.Qs[r][kk + qk];     af[1] = su.s1.Qs[r + 8][kk + qk];
        af[2] = su.s1.Qs[r][kk + qk + 4]; af[3] = su.s1.Qs[r + 8][kk + qk + 4];
        #pragma unroll
        for (int t = 0; t < 13; t++) {
            int gt = gt0 + t;
            if (gt < gt1) {
                uint32_t bf[2];
                bf[0] = su.s1.Ks[kk + qk][gt * 8 + grp];
                bf[1] = su.s1.Ks[kk + qk + 4][gt * 8 + grp];
                mma_tf32(sacc[t], af, bf);
            }
        }
    }

    // ---- scatter valid scores (+rpb) into ssc ----
    {
        int r0 = mt * 16 + grp, r1 = r0 + 8;
        int i_a = i0 + (r0 >> 3), j_a = j0 + (r0 & 7);
        int ni_a = i_a - 3; ni_a = ni_a < 0 ? 0 : (ni_a > 57 ? 57 : ni_a);
        int nj_a = j_a - 3; nj_a = nj_a < 0 ? 0 : (nj_a > 57 ? 57 : nj_a);
        int di_a = ni_a - wi0, dj_a = nj_a - wj0;
        int rb_a = (ni_a - i_a + 6) * 13 + (nj_a - j_a + 6);
        int i_b = i0 + (r1 >> 3), j_b = j0 + (r1 & 7);
        int ni_b = i_b - 3; ni_b = ni_b < 0 ? 0 : (ni_b > 57 ? 57 : ni_b);
        int nj_b = j_b - 3; nj_b = nj_b < 0 ? 0 : (nj_b > 57 ? 57 : nj_b);
        int di_b = ni_b - wi0, dj_b = nj_b - wj0;
        int rb_b = (ni_b - i_b + 6) * 13 + (nj_b - j_b + 6);

        #pragma unroll
        for (int t = 0; t < 13; t++) {
            int gt = gt0 + t;
            if (gt >= gt1) break;
            #pragma unroll
            for (int cc = 0; cc < 2; cc++) {
                int col = gt * 8 + 2 * qk + cc;
                int rw = (col * 2341) >> 15;
                int cw = col - rw * 14;
                // row r0
                {
                    int a = rw - di_a, b = cw - dj_a;
                    if ((unsigned)a < 7u && (unsigned)b < 7u)
                        ssc[r0][a * 7 + b] = sacc[t][cc] + srpb[rb_a + a * 13 + b];
                }
                // row r1
                {
                    int a = rw - di_b, b = cw - dj_b;
                    if ((unsigned)a < 7u && (unsigned)b < 7u)
                        ssc[r1][a * 7 + b] = sacc[t][2 + cc] + srpb[rb_b + a * 13 + b];
                }
            }
        }
    }
    __syncthreads();

    // ---- load V window (overwrites Q/K smem) ----
    #pragma unroll
    for (int idx = tid; idx < 196 * 32; idx += 256) {
        int widx = idx >> 5, c = idx & 31;
        int rw = (widx * 2341) >> 15;
        int cw = widx - rw * 14;
        int gi = wi0 + rw; gi = gi > 63 ? 63 : gi;
        int gj = wj0 + cw; gj = gj > 63 ? 63 : gj;
        su.Vs[widx][c] = qb[(size_t)(gi * 64 + gj) * 384 + 256 + c];
    }
    __syncthreads();

    // ---- softmax + AV (warp per 8 pixels) ----
    int pix0 = warp * 8;
    #pragma unroll
    for (int pp = 0; pp < 8; pp++) {
        int p = pix0 + pp;
        int i = i0 + (p >> 3), j = j0 + (p & 7);
        int ni = i - 3; ni = ni < 0 ? 0 : (ni > 57 ? 57 : ni);
        int nj = j - 3; nj = nj < 0 ? 0 : (nj > 57 ? 57 : nj);
        int nbase = (ni - wi0) * 14 + (nj - wj0);

        float a0 = ssc[p][lane];
        float a1 = (lane < 17) ? ssc[p][lane + 32] : -1e30f;
        float m = fmaxf(a0, a1);
        #pragma unroll
        for (int o = 16; o > 0; o >>= 1) m = fmaxf(m, __shfl_xor_sync(0xffffffffu, m, o));
        float e0 = __expf(a0 - m);
        float e1 = (lane < 17) ? __expf(a1 - m) : 0.f;
        float ps = e0 + e1;
        #pragma unroll
        for (int o = 16; o > 0; o >>= 1) ps += __shfl_xor_sync(0xffffffffu, ps, o);
        float inv = 1.0f / ps;
        ssc[p][lane] = e0 * inv;
        if (lane < 17) ssc[p][lane + 32] = e1 * inv;
        __syncwarp();

        float out = 0.f;
        #pragma unroll
        for (int a = 0; a < KS; a++) {
            #pragma unroll
            for (int bcol = 0; bcol < KS; bcol++) {
                out = fmaf(ssc[p][a * KS + bcol], su.Vs[nbase + a * 14 + bcol][lane], out);
            }
        }
        na[(size_t)(n * HWP + i * 64 + j) * CDIM + h * DH + lane] = out;
    }
}

// ---------------------------------------------------------------------------
// Fused proj GEMM + channel-attn gate + residual combine + LayerNorm2.
// ---------------------------------------------------------------------------
__global__ __launch_bounds__(128)
void k_proj_ln(const float* __restrict__ A /*na*/, const float* __restrict__ B /*proj_w*/,
               const float* __restrict__ bias,
               const float* __restrict__ xs, const float* __restrict__ t,
               const float* __restrict__ gsum,
               const float* __restrict__ ca1w, const float* __restrict__ ca1b,
               const float* __restrict__ ca2w, const float* __restrict__ ca2b,
               const float* __restrict__ w2, const float* __restrict__ b2,
               float* __restrict__ x2, float* __restrict__ xn2)
{
    __shared__ union SU {
        struct { uint32_t As[64][36]; uint32_t Bs[32][136]; } gm;
        float x2s[64][132];
    } sm;
    __shared__ float sgm[CDIM];
    __shared__ float sr7[7];
    __shared__ float sgarr[CDIM];

    int tid  = threadIdx.x;
    int lane = tid & 31;
    int warp = tid >> 5;
    int grp = lane >> 2, qk = lane & 3;
    int m0 = blockIdx.x * 64;
    int n = m0 >> 12;

    float acc[16][4];
    #pragma unroll
    for (int nt = 0; nt < 16; nt++)
        #pragma unroll
        for (int i = 0; i < 4; i++) acc[nt][i] = 0.f;

    int arow = tid >> 1, kseg = (tid & 1) * 16;
    int brow = tid >> 2, bcol = (tid & 3) * 32;

    for (int k0 = 0; k0 < 128; k0 += 32) {
        const float* ap = A + (size_t)(m0 + arow) * CDIM + k0 + kseg;
        #pragma unroll
        for (int i = 0; i < 4; i++) {
            float4 v = *(const float4*)(ap + i * 4);
            sm.gm.As[arow][kseg + i * 4 + 0] = f2tf32(v.x);
            sm.gm.As[arow][kseg + i * 4 + 1] = f2tf32(v.y);
            sm.gm.As[arow][kseg + i * 4 + 2] = f2tf32(v.z);
            sm.gm.As[arow][kseg + i * 4 + 3] = f2tf32(v.w);
        }
        const float* bp = B + (size_t)(k0 + brow) * CDIM + bcol;
        #pragma unroll
        for (int i = 0; i < 8; i++) {
            float4 v = *(const float4*)(bp + i * 4);
            sm.gm.Bs[brow][bcol + i * 4 + 0] = f2tf32(v.x);
            sm.gm.Bs[brow][bcol + i * 4 + 1] = f2tf32(v.y);
            sm.gm.Bs[brow][bcol + i * 4 + 2] = f2tf32(v.z);
            sm.gm.Bs[brow][bcol + i * 4 + 3] = f2tf32(v.w);
        }
        __syncthreads();
        #pragma unroll
        for (int kk = 0; kk < 32; kk += 8) {
            uint32_t af[4];
            int r = warp * 16 + grp;
            af[0] = sm.gm.As[r][kk + qk];     af[1] = sm.gm.As[r + 8][kk + qk];
            af[2] = sm.gm.As[r][kk + qk + 4]; af[3] = sm.gm.As[r + 8][kk + qk + 4];
            #pragma unroll
            for (int nt = 0; nt < 16; nt++) {
                uint32_t bf[2];
                bf[0] = sm.gm.Bs[kk + qk][nt * 8 + grp];
                bf[1] = sm.gm.Bs[kk + qk + 4][nt * 8 + grp];
                mma_tf32(acc[nt], af, bf);
            }
        }
        __syncthreads();
    }

    // ---- compute channel-attention gate in-block ----
    sgm[tid] = gsum[n * CDIM + tid] * (1.0f / HWP);
    __syncthreads();
    if (warp == 0) {
        float part[7];
        #pragma unroll
        for (int j = 0; j < 7; j++) part[j] = 0.f;
        #pragma unroll
        for (int k = 0; k < 4; k++) {
            int c = lane + 32 * k;
            float gv = sgm[c];
            #pragma unroll
            for (int j = 0; j < 7; j++) part[j] += gv * ca1w[c * 7 + j];
        }
        #pragma unroll
        for (int j = 0; j < 7; j++) {
            #pragma unroll
            for (int o = 16; o > 0; o >>= 1)
                part[j] += __shfl_xor_sync(0xffffffffu, part[j], o);
        }
        if (lane == 0) {
            #pragma unroll
            for (int j = 0; j < 7; j++) sr7[j] = fmaxf(part[j] + ca1b[j], 0.f);
        }
    }
    __syncthreads();
    {
        float s = ca2b[tid];
        #pragma unroll
        for (int j = 0; j < 7; j++) s += sr7[j] * ca2w[j * CDIM + tid];
        sgarr[tid] = (1.0f / (1.0f + expf(-s))) * 0.02f;
    }
    __syncthreads();

    // epilogue: x2 value = acc + bias + xs + t*g -> smem
    {
        int r = warp * 16 + grp;
        size_t ro0 = (size_t)(m0 + r) * CDIM;
        size_t ro1 = (size_t)(m0 + r + 8) * CDIM;
        #pragma unroll
        for (int nt = 0; nt < 16; nt++) {
            int c = nt * 8 + 2 * qk;
            float bb0 = bias[c], bb1 = bias[c + 1];
            float g0 = sgarr[c], g1 = sgarr[c + 1];
            sm.x2s[r][c]         = acc[nt][0] + bb0 + xs[ro0 + c]     + t[ro0 + c]     * g0;
            sm.x2s[r][c + 1]     = acc[nt][1] + bb1 + xs[ro0 + c + 1] + t[ro0 + c + 1] * g1;
            sm.x2s[r + 8][c]     = acc[nt][2] + bb0 + xs[ro1 + c]     + t[ro1 + c]     * g0;
            sm.x2s[r + 8][c + 1] = acc[nt][3] + bb1 + xs[ro1 + c + 1] + t[ro1 + c + 1] * g1;
        }
    }
    __syncthreads();

    float w2r[4], b2r[4];
    #pragma unroll
    for (int k = 0; k < 4; k++) { w2r[k] = w2[lane + 32 * k]; b2r[k] = b2[lane + 32 * k]; }

    #pragma unroll
    for (int rr = 0; rr < 16; rr++) {
        int r = warp * 16 + rr;
        float v[4];
        float sum = 0.f, sq = 0.f;
        #pragma unroll
        for (int k = 0; k < 4; k++) {
            v[k] = sm.x2s[r][lane + 32 * k];
            sum += v[k]; sq += v[k] * v[k];
        }
        #pragma unroll
        for (int o = 16; o > 0; o >>= 1) {
            sum += __shfl_xor_sync(0xffffffffu, sum, o);
            sq  += __shfl_xor_sync(0xffffffffu, sq, o);
        }
        float mu = sum * (1.0f / CDIM);
        float rs = rsqrtf(sq * (1.0f / CDIM) - mu * mu + 1e-5f);
        size_t ro = (size_t)(m0 + r) * CDIM;
        #pragma unroll
        for (int k = 0; k < 4; k++) {
            x2[ro + lane + 32 * k]  = v[k];
            xn2[ro + lane + 32 * k] = (v[k] - mu) * rs * w2r[k] + b2r[k];
        }
    }
}

// ---------------------------------------------------------------------------
// Launch
// ---------------------------------------------------------------------------
extern "C" void kernel_launch(void* const* d_in, const int* in_sizes, int n_in,
                              void* d_out, int out_size)
{
    const float* x      = (const float*)d_in[0];
    const float* ln1_w  = (const float*)d_in[1];
    const float* ln1_b  = (const float*)d_in[2];
    const float* ln2_w  = (const float*)d_in[3];
    const float* ln2_b  = (const float*)d_in[4];
    const float* qkv_w  = (const float*)d_in[5];
    const float* qkv_b  = (const float*)d_in[6];
    const float* proj_w = (const float*)d_in[7];
    const float* proj_b = (const float*)d_in[8];
    const float* rpb    = (const float*)d_in[9];
    const float* conv1_w= (const float*)d_in[10];
    const float* conv1_b= (const float*)d_in[11];
    const float* conv2_w= (const float*)d_in[12];
    const float* conv2_b= (const float*)d_in[13];
    const float* ca1_w  = (const float*)d_in[14];
    const float* ca1_b  = (const float*)d_in[15];
    const float* ca2_w  = (const float*)d_in[16];
    const float* ca2_b  = (const float*)d_in[17];
    const float* fc1_w  = (const float*)d_in[18];
    const float* fc1_b  = (const float*)d_in[19];
    const float* fc2_w  = (const float*)d_in[20];
    const float* fc2_b  = (const float*)d_in[21];
    float* out = (float*)d_out;

    float* scr = nullptr;
    cudaGetSymbolAddress((void**)&scr, d_scratch);
    float* xs   = scr + OFF_XS;
    float* xn   = scr + OFF_XN;
    float* qkv  = scr + OFF_QKV;
    float* t    = scr + OFF_T;
    float* na   = scr + OFF_NA;
    float* x2   = scr + OFF_X2;
    float* xn2  = scr + OFF_XN2;
    float* h1   = scr + OFF_H1;
    float* gsum = scr + OFF_GSUM;

    // 1. transpose + LN1 (+ zero gsum)
    k_transpose_ln<<<ROWS / 32, 128>>>(x, ln1_w, ln1_b, xs, xn, gsum);
    // 2. qkv GEMM: 16384 x 384 x 128
    k_mma<EPI_NONE><<<dim3(6, ROWS / 64), 128>>>(xn, qkv_w, qkv_b, qkv,
                                                 ROWS, 384, 128, nullptr);
    // 3. fused conv1+gelu+conv2+colsum
    k_conv<<<ROWS / 64, 128>>>(xn, conv1_w, conv1_b, conv2_w, conv2_b, t, gsum);
    // 4. neighborhood attention (tensor-core scores)
    k_na<<<dim3(64, NB * NHEAD), 256>>>(qkv, rpb, na);
    // 5. fused proj + gate + residual + LN2
    k_proj_ln<<<ROWS / 64, 128>>>(na, proj_w, proj_b, xs, t, gsum,
                                  ca1_w, ca1_b, ca2_w, ca2_b,
                                  ln2_w, ln2_b, x2, xn2);
    // 6. fc1 + gelu: 16384 x 512 x 128
    k_mma<EPI_GELU><<<dim3(8, ROWS / 64), 128>>>(xn2, fc1_w, fc1_b, h1,
                                                 ROWS, 512, 128, nullptr);
    // 7. fc2 + residual, write NCHW output
    k_mma<EPI_OUT><<<dim3(2, ROWS / 64), 128>>>(h1, fc2_w, fc2_b, out,
                                                ROWS, 128, 512, x2);
}

// round 6
// speedup vs baseline: 2.0326x; 1.0026x over previous
#include <cuda_runtime.h>
#include <math.h>
#include <stdint.h>

// ---------------------------------------------------------------------------
// Problem constants
// ---------------------------------------------------------------------------
#define NB    4
#define CDIM  128
#define HWP   4096           // 64*64
#define ROWS  (NB * HWP)     // 16384
#define NHEAD 4
#define DH    32
#define KS    7

// Scratch arena layout (floats)
#define OFF_XS    0u
#define OFF_XN    2097152u            // 16384*128
#define OFF_QKV   4194304u            // len 16384*384
#define OFF_T     11010048u           // len 16384*128
#define OFF_NA    13107200u
#define OFF_X2    15204352u
#define OFF_XN2   17301504u
#define OFF_H1    19398656u           // len 16384*512
#define OFF_GSUM  27787264u           // 512
#define SCRATCH_FLOATS 27788288u

__device__ float d_scratch[SCRATCH_FLOATS];

__device__ __forceinline__ float gelu_exact(float x) {
    return 0.5f * x * (1.0f + erff(x * 0.7071067811865476f));
}

__device__ __forceinline__ uint32_t f2tf32(float f) {
    uint32_t r;
    asm("cvt.rna.tf32.f32 %0, %1;" : "=r"(r) : "f"(f));
    return r;
}

__device__ __forceinline__ void mma_tf32(float d[4], const uint32_t a[4], const uint32_t b[2]) {
    asm volatile(
        "mma.sync.aligned.m16n8k8.row.col.f32.tf32.tf32.f32 "
        "{%0,%1,%2,%3},{%4,%5,%6,%7},{%8,%9},{%0,%1,%2,%3};\n"
        : "+f"(d[0]), "+f"(d[1]), "+f"(d[2]), "+f"(d[3])
        : "r"(a[0]), "r"(a[1]), "r"(a[2]), "r"(a[3]), "r"(b[0]), "r"(b[1]));
}

// ---------------------------------------------------------------------------
// Kernel 1: NCHW -> NHWC transpose + LayerNorm1.  32 pixels per block.
// ---------------------------------------------------------------------------
__global__ __launch_bounds__(128)
void k_transpose_ln(const float* __restrict__ x,
                    const float* __restrict__ w, const float* __restrict__ b,
                    float* __restrict__ xs, float* __restrict__ xn,
                    float* __restrict__ gsum)
{
    __shared__ float s[32][129];
    __shared__ float smu[32], srs[32];
    int tid = threadIdx.x;
    if (blockIdx.x == 0) {
        #pragma unroll
        for (int i = 0; i < 4; i++) gsum[tid + i * 128] = 0.f;
    }
    int row0 = blockIdx.x * 32;
    int n  = row0 >> 12;
    int p0 = row0 & 4095;
    int pl = tid & 31;
    int cg = tid >> 5;       // 0..3

    #pragma unroll 4
    for (int it = 0; it < 32; it++) {
        int c = it * 4 + cg;
        s[pl][c] = x[((size_t)(n * CDIM + c) << 12) + p0 + pl];
    }
    __syncthreads();

    if (tid < 32) {
        float sum = 0.f, sq = 0.f;
        #pragma unroll 8
        for (int c = 0; c < CDIM; c++) { float v = s[tid][c]; sum += v; sq += v * v; }
        float mu  = sum * (1.0f / CDIM);
        float var = sq * (1.0f / CDIM) - mu * mu;
        smu[tid] = mu;
        srs[tid] = rsqrtf(var + 1e-5f);
    }
    __syncthreads();

    float wc = w[tid], bc = b[tid];
    #pragma unroll 4
    for (int it = 0; it < 32; it++) {
        float v = s[it][tid];
        size_t o = (size_t)(row0 + it) * CDIM + tid;
        xs[o] = v;
        xn[o] = (v - smu[it]) * srs[it] * wc + bc;
    }
}

// ---------------------------------------------------------------------------
// Pipelined tf32 GEMM: BM=64, BN=64, BK=32, 128 threads (2x2 warps).
// ---------------------------------------------------------------------------
#define EPI_NONE 0
#define EPI_GELU 1
#define EPI_OUT  3   // out NCHW = acc+bias + e1(x2)

template<int EPI>
__device__ __forceinline__ void epi_write(float* __restrict__ C, int row, int col,
                                          int N, float v, const float* __restrict__ e1)
{
    if (EPI == EPI_GELU) {
        C[(size_t)row * N + col] = gelu_exact(v);
    } else if (EPI == EPI_NONE) {
        C[(size_t)row * N + col] = v;
    } else { // EPI_OUT: write NCHW
        v += e1[(size_t)row * CDIM + col];
        int bn = row >> 12, p = row & 4095;
        C[((size_t)(bn * CDIM + col) << 12) + p] = v;
    }
}

template<int EPI>
__global__ __launch_bounds__(128)
void k_mma(const float* __restrict__ A, const float* __restrict__ B,
           const float* __restrict__ bias, float* __restrict__ C,
           int M, int N, int K, const float* __restrict__ e1)
{
    constexpr int BM = 64, BN = 64, BK = 32;
    __shared__ uint32_t As[BM][BK + 4];
    __shared__ uint32_t Bs[BK][BN + 8];

    int tid  = threadIdx.x;
    int lane = tid & 31;
    int warp = tid >> 5;
    int wm = warp & 1, wn = warp >> 1;
    int m0 = blockIdx.y * BM, n0 = blockIdx.x * BN;
    int grp = lane >> 2, qk = lane & 3;

    float d[2][4][4];
    #pragma unroll
    for (int mt = 0; mt < 2; mt++)
        #pragma unroll
        for (int nt = 0; nt < 4; nt++)
            #pragma unroll
            for (int i = 0; i < 4; i++) d[mt][nt][i] = 0.f;

    int arow = tid >> 1, kseg = (tid & 1) * 16;
    int brow = tid >> 2, bcol = (tid & 3) * 16;

    float4 pa0, pa1, pa2, pa3, pb0, pb1, pb2, pb3;

#define LDG_TILE(k0) { \
    const float* ap = A + (size_t)(m0 + arow) * K + (k0) + kseg; \
    pa0 = *(const float4*)ap;       pa1 = *(const float4*)(ap + 4); \
    pa2 = *(const float4*)(ap + 8); pa3 = *(const float4*)(ap + 12); \
    const float* bp = B + (size_t)((k0) + brow) * N + n0 + bcol; \
    pb0 = *(const float4*)bp;       pb1 = *(const float4*)(bp + 4); \
    pb2 = *(const float4*)(bp + 8); pb3 = *(const float4*)(bp + 12); }

#define STS_TILE() { \
    As[arow][kseg+0]=f2tf32(pa0.x);  As[arow][kseg+1]=f2tf32(pa0.y);  As[arow][kseg+2]=f2tf32(pa0.z);  As[arow][kseg+3]=f2tf32(pa0.w); \
    As[arow][kseg+4]=f2tf32(pa1.x);  As[arow][kseg+5]=f2tf32(pa1.y);  As[arow][kseg+6]=f2tf32(pa1.z);  As[arow][kseg+7]=f2tf32(pa1.w); \
    As[arow][kseg+8]=f2tf32(pa2.x);  As[arow][kseg+9]=f2tf32(pa2.y);  As[arow][kseg+10]=f2tf32(pa2.z); As[arow][kseg+11]=f2tf32(pa2.w); \
    As[arow][kseg+12]=f2tf32(pa3.x); As[arow][kseg+13]=f2tf32(pa3.y); As[arow][kseg+14]=f2tf32(pa3.z); As[arow][kseg+15]=f2tf32(pa3.w); \
    Bs[brow][bcol+0]=f2tf32(pb0.x);  Bs[brow][bcol+1]=f2tf32(pb0.y);  Bs[brow][bcol+2]=f2tf32(pb0.z);  Bs[brow][bcol+3]=f2tf32(pb0.w); \
    Bs[brow][bcol+4]=f2tf32(pb1.x);  Bs[brow][bcol+5]=f2tf32(pb1.y);  Bs[brow][bcol+6]=f2tf32(pb1.z);  Bs[brow][bcol+7]=f2tf32(pb1.w); \
    Bs[brow][bcol+8]=f2tf32(pb2.x);  Bs[brow][bcol+9]=f2tf32(pb2.y);  Bs[brow][bcol+10]=f2tf32(pb2.z); Bs[brow][bcol+11]=f2tf32(pb2.w); \
    Bs[brow][bcol+12]=f2tf32(pb3.x); Bs[brow][bcol+13]=f2tf32(pb3.y); Bs[brow][bcol+14]=f2tf32(pb3.z); Bs[brow][bcol+15]=f2tf32(pb3.w); }

#define MMA_TILE() { \
    _Pragma("unroll") \
    for (int kk = 0; kk < BK; kk += 8) { \
        uint32_t af[2][4], bf[4][2]; \
        _Pragma("unroll") \
        for (int mt = 0; mt < 2; mt++) { \
            int r = wm * 32 + mt * 16 + grp; \
            af[mt][0] = As[r][kk + qk];     af[mt][1] = As[r + 8][kk + qk]; \
            af[mt][2] = As[r][kk + qk + 4]; af[mt][3] = As[r + 8][kk + qk + 4]; \
        } \
        _Pragma("unroll") \
        for (int nt = 0; nt < 4; nt++) { \
            int cidx = wn * 32 + nt * 8 + grp; \
            bf[nt][0] = Bs[kk + qk][cidx]; bf[nt][1] = Bs[kk + qk + 4][cidx]; \
        } \
        _Pragma("unroll") \
        for (int mt = 0; mt < 2; mt++) \
            _Pragma("unroll") \
            for (int nt = 0; nt < 4; nt++) \
                mma_tf32(d[mt][nt], af[mt], bf[nt]); \
    } }

    LDG_TILE(0);
    STS_TILE();
    __syncthreads();
    for (int k0 = BK; k0 < K; k0 += BK) {
        LDG_TILE(k0);
        MMA_TILE();
        __syncthreads();
        STS_TILE();
        __syncthreads();
    }
    MMA_TILE();

#undef LDG_TILE
#undef STS_TILE
#undef MMA_TILE

    #pragma unroll
    for (int mt = 0; mt < 2; mt++) {
        int rbase = m0 + wm * 32 + mt * 16 + grp;
        #pragma unroll
        for (int nt = 0; nt < 4; nt++) {
            int cbase = n0 + wn * 32 + nt * 8 + 2 * qk;
            float b0 = bias[cbase], b1 = bias[cbase + 1];
            epi_write<EPI>(C, rbase,     cbase,     N, d[mt][nt][0] + b0, e1);
            epi_write<EPI>(C, rbase,     cbase + 1, N, d[mt][nt][1] + b1, e1);
            epi_write<EPI>(C, rbase + 8, cbase,     N, d[mt][nt][2] + b0, e1);
            epi_write<EPI>(C, rbase + 8, cbase + 1, N, d[mt][nt][3] + b1, e1);
        }
    }
}

// ---------------------------------------------------------------------------
// Fused conv1 + GELU + conv2 + spatial-mean.  64 rows per block, 128 threads.
// ---------------------------------------------------------------------------
__global__ __launch_bounds__(128)
void k_conv(const float* __restrict__ xn,
            const float* __restrict__ w1, const float* __restrict__ b1,
            const float* __restrict__ w2, const float* __restrict__ b2,
            float* __restrict__ tout, float* __restrict__ gsum)
{
    __shared__ uint32_t As[64][36];
    __shared__ uint32_t Bs1[32][40];
    __shared__ uint32_t St1[64][36];
    __shared__ uint32_t Bs2[32][136];

    int tid  = threadIdx.x;
    int lane = tid & 31;
    int warp = tid >> 5;
    int grp = lane >> 2, qk = lane & 3;
    int m0 = blockIdx.x * 64;

    {
        int r = tid >> 2, c0 = (tid & 3) * 32;
        #pragma unroll
        for (int i = 0; i < 8; i++) {
            float4 v = *(const float4*)(w2 + (size_t)r * 128 + c0 + i * 4);
            Bs2[r][c0 + i * 4 + 0] = f2tf32(v.x);
            Bs2[r][c0 + i * 4 + 1] = f2tf32(v.y);
            Bs2[r][c0 + i * 4 + 2] = f2tf32(v.z);
            Bs2[r][c0 + i * 4 + 3] = f2tf32(v.w);
        }
    }

    float acc1[4][4];
    #pragma unroll
    for (int nt = 0; nt < 4; nt++)
        #pragma unroll
        for (int i = 0; i < 4; i++) acc1[nt][i] = 0.f;

    int arow = tid >> 1, kseg = (tid & 1) * 16;
    int b1row = tid >> 2, b1col = (tid & 3) * 8;

    for (int k0 = 0; k0 < 128; k0 += 32) {
        const float* ap = xn + (size_t)(m0 + arow) * CDIM + k0 + kseg;
        #pragma unroll
        for (int i = 0; i < 4; i++) {
            float4 v = *(const float4*)(ap + i * 4);
            As[arow][kseg + i * 4 + 0] = f2tf32(v.x);
            As[arow][kseg + i * 4 + 1] = f2tf32(v.y);
            As[arow][kseg + i * 4 + 2] = f2tf32(v.z);
            As[arow][kseg + i * 4 + 3] = f2tf32(v.w);
        }
        const float* bp = w1 + (size_t)(k0 + b1row) * 32 + b1col;
        #pragma unroll
        for (int i = 0; i < 2; i++) {
            float4 v = *(const float4*)(bp + i * 4);
            Bs1[b1row][b1col + i * 4 + 0] = f2tf32(v.x);
            Bs1[b1row][b1col + i * 4 + 1] = f2tf32(v.y);
            Bs1[b1row][b1col + i * 4 + 2] = f2tf32(v.z);
            Bs1[b1row][b1col + i * 4 + 3] = f2tf32(v.w);
        }
        __syncthreads();
        #pragma unroll
        for (int kk = 0; kk < 32; kk += 8) {
            uint32_t af[4], bf[4][2];
            int r = warp * 16 + grp;
            af[0] = As[r][kk + qk];     af[1] = As[r + 8][kk + qk];
            af[2] = As[r][kk + qk + 4]; af[3] = As[r + 8][kk + qk + 4];
            #pragma unroll
            for (int nt = 0; nt < 4; nt++) {
                bf[nt][0] = Bs1[kk + qk][nt * 8 + grp];
                bf[nt][1] = Bs1[kk + qk + 4][nt * 8 + grp];
            }
            #pragma unroll
            for (int nt = 0; nt < 4; nt++) mma_tf32(acc1[nt], af, bf[nt]);
        }
        __syncthreads();
    }

    {
        int r = warp * 16 + grp;
        #pragma unroll
        for (int nt = 0; nt < 4; nt++) {
            int c = nt * 8 + 2 * qk;
            float bb0 = b1[c], bb1 = b1[c + 1];
            St1[r][c]         = f2tf32(gelu_exact(acc1[nt][0] + bb0));
            St1[r][c + 1]     = f2tf32(gelu_exact(acc1[nt][1] + bb1));
            St1[r + 8][c]     = f2tf32(gelu_exact(acc1[nt][2] + bb0));
            St1[r + 8][c + 1] = f2tf32(gelu_exact(acc1[nt][3] + bb1));
        }
    }
    __syncthreads();

    float acc2[16][4];
    #pragma unroll
    for (int nt = 0; nt < 16; nt++)
        #pragma unroll
        for (int i = 0; i < 4; i++) acc2[nt][i] = 0.f;

    #pragma unroll
    for (int kk = 0; kk < 32; kk += 8) {
        uint32_t af[4];
        int r = warp * 16 + grp;
        af[0] = St1[r][kk + qk];     af[1] = St1[r + 8][kk + qk];
        af[2] = St1[r][kk + qk + 4]; af[3] = St1[r + 8][kk + qk + 4];
        #pragma unroll
        for (int nt = 0; nt < 16; nt++) {
            uint32_t bf[2];
            bf[0] = Bs2[kk + qk][nt * 8 + grp];
            bf[1] = Bs2[kk + qk + 4][nt * 8 + grp];
            mma_tf32(acc2[nt], af, bf);
        }
    }

    int n = m0 >> 12;
    int r = warp * 16 + grp;
    #pragma unroll
    for (int nt = 0; nt < 16; nt++) {
        int c = nt * 8 + 2 * qk;
        float bb0 = b2[c], bb1 = b2[c + 1];
        float v0 = acc2[nt][0] + bb0, v1 = acc2[nt][1] + bb1;
        float v2 = acc2[nt][2] + bb0, v3 = acc2[nt][3] + bb1;
        size_t ro = (size_t)(m0 + r) * CDIM;
        tout[ro + c] = v0;             tout[ro + c + 1] = v1;
        tout[ro + 8 * CDIM + c] = v2;  tout[ro + 8 * CDIM + c + 1] = v3;
        float s0 = v0 + v2, s1 = v1 + v3;
        #pragma unroll
        for (int o = 4; o < 32; o <<= 1) {
            s0 += __shfl_xor_sync(0xffffffffu, s0, o);
            s1 += __shfl_xor_sync(0xffffffffu, s1, o);
        }
        if (lane < 4) {
            atomicAdd(&gsum[n * CDIM + c], s0);
            atomicAdd(&gsum[n * CDIM + c + 1], s1);
        }
    }
}

// ---------------------------------------------------------------------------
// Neighborhood attention — fully tensor-core.
// Block = (8x8 tile, batch, head), 256 threads.
// S = Q(64x32) @ Kwin^T(32x200) -> dense P (exp, tf32) -> O = P @ V(200x32).
// Dynamic smem: P[64][204] | union{ Qs[64][36]+Ks[32][204] , Vs[200][40] } | rpb | sinv
// ---------------------------------------------------------------------------
#define NA_P_OFF   0
#define NA_Q_OFF   52224
#define NA_K_OFF   61440
#define NA_V_OFF   52224
#define NA_RPB_OFF 87552
#define NA_INV_OFF 88228
#define NA_SMEM    88512

__global__ __launch_bounds__(256)
void k_na(const float* __restrict__ qkv, const float* __restrict__ rpb,
          float* __restrict__ na)
{
    extern __shared__ char smem[];
    uint32_t (*P)[204]  = (uint32_t(*)[204])(smem + NA_P_OFF);
    uint32_t (*Qs)[36]  = (uint32_t(*)[36])(smem + NA_Q_OFF);
    uint32_t (*Ks)[204] = (uint32_t(*)[204])(smem + NA_K_OFF);
    uint32_t (*Vs)[40]  = (uint32_t(*)[40])(smem + NA_V_OFF);
    float* srpb = (float*)(smem + NA_RPB_OFF);
    float* sinv = (float*)(smem + NA_INV_OFF);

    int tid  = threadIdx.x;
    int lane = tid & 31;
    int warp = tid >> 5;
    int grp = lane >> 2, qk = lane & 3;

    int n = blockIdx.y >> 2;
    int h = blockIdx.y & 3;
    int i0 = (blockIdx.x >> 3) * 8, j0 = (blockIdx.x & 7) * 8;
    int wi0 = i0 - 3; wi0 = wi0 < 0 ? 0 : wi0;
    int wj0 = j0 - 3; wj0 = wj0 < 0 ? 0 : wj0;

    if (tid < 169) srpb[tid] = rpb[h * 169 + tid];

    const float* qb = qkv + (size_t)(n * HWP) * 384 + h * DH;

    // ---- load Q (scaled, tf32) ----
    #pragma unroll
    for (int idx = tid; idx < 64 * 32; idx += 256) {
        int p = idx >> 5, c = idx & 31;
        int i = i0 + (p >> 3), j = j0 + (p & 7);
        Qs[p][c] = f2tf32(qb[(size_t)(i * 64 + j) * 384 + c] * 0.17677669529663687f);
    }
    // ---- load K transposed: thread handles 4 channels of one widx ----
    for (int idx = tid; idx < 8 * 200; idx += 256) {
        int chunk = idx / 200;
        int widx  = idx - chunk * 200;
        int c0 = chunk * 4;
        int rw = (widx * 2341) >> 15; rw = rw > 13 ? 13 : rw;
        int cw = widx - rw * 14;
        int gi = wi0 + rw; gi = gi > 63 ? 63 : gi;
        int gj = wj0 + cw; gj = gj > 63 ? 63 : gj;
        float4 v = *(const float4*)(qb + (size_t)(gi * 64 + gj) * 384 + 128 + c0);
        Ks[c0 + 0][widx] = f2tf32(v.x);
        Ks[c0 + 1][widx] = f2tf32(v.y);
        Ks[c0 + 2][widx] = f2tf32(v.z);
        Ks[c0 + 3][widx] = f2tf32(v.w);
    }
    __syncthreads();

    // ---- S-MMA: warp (mt rows, nh col-half) ----
    int mt = warp >> 1;
    int nh = warp & 1;
    int gt0 = nh ? 12 : 0;
    int ngt = nh ? 13 : 12;

    float sacc[13][4];
    #pragma unroll
    for (int t = 0; t < 13; t++)
        #pragma unroll
        for (int i = 0; i < 4; i++) sacc[t][i] = 0.f;

    #pragma unroll
    for (int kk = 0; kk < 32; kk += 8) {
        uint32_t af[4];
        int r = mt * 16 + grp;
        af[0] = Qs[r][kk + qk];     af[1] = Qs[r + 8][kk + qk];
        af[2] = Qs[r][kk + qk + 4]; af[3] = Qs[r + 8][kk + qk + 4];
        #pragma unroll
        for (int t = 0; t < 13; t++) {
            if (t < ngt) {
                int gt = gt0 + t;
                uint32_t bf[2];
                bf[0] = Ks[kk + qk][gt * 8 + grp];
                bf[1] = Ks[kk + qk + 4][gt * 8 + grp];
                mma_tf32(sacc[t], af, bf);
            }
        }
    }

    // ---- dense store: P[row][col] = score+rpb if valid else -1e30 ----
    {
        int r0 = mt * 16 + grp, r1 = r0 + 8;
        int i_a = i0 + (r0 >> 3), j_a = j0 + (r0 & 7);
        int ni_a = i_a - 3; ni_a = ni_a < 0 ? 0 : (ni_a > 57 ? 57 : ni_a);
        int nj_a = j_a - 3; nj_a = nj_a < 0 ? 0 : (nj_a > 57 ? 57 : nj_a);
        int di_a = ni_a - wi0, dj_a = nj_a - wj0;
        int rb_a = (ni_a - i_a + 6) * 13 + (nj_a - j_a + 6);
        int i_b = i0 + (r1 >> 3), j_b = j0 + (r1 & 7);
        int ni_b = i_b - 3; ni_b = ni_b < 0 ? 0 : (ni_b > 57 ? 57 : ni_b);
        int nj_b = j_b - 3; nj_b = nj_b < 0 ? 0 : (nj_b > 57 ? 57 : nj_b);
        int di_b = ni_b - wi0, dj_b = nj_b - wj0;
        int rb_b = (ni_b - i_b + 6) * 13 + (nj_b - j_b + 6);

        #pragma unroll
        for (int t = 0; t < 13; t++) {
            if (t >= ngt) break;
            int gt = gt0 + t;
            #pragma unroll
            for (int cc = 0; cc < 2; cc++) {
                int col = gt * 8 + 2 * qk + cc;
                int rw = (col * 2341) >> 15;
                int cw = col - rw * 14;
                int a0 = rw - di_a, b0 = cw - dj_a;
                float v0 = ((unsigned)a0 < 7u && (unsigned)b0 < 7u)
                         ? sacc[t][cc] + srpb[rb_a + a0 * 13 + b0] : -1e30f;
                P[r0][col] = __float_as_uint(v0);
                int a1 = rw - di_b, b1 = cw - dj_b;
                float v1 = ((unsigned)a1 < 7u && (unsigned)b1 < 7u)
                         ? sacc[t][2 + cc] + srpb[rb_b + a1 * 13 + b1] : -1e30f;
                P[r1][col] = __float_as_uint(v1);
            }
        }
    }
    __syncthreads();   // P complete, Ks/Qs free

    // ---- load V (tf32) into Vs[200][40] ----
    #pragma unroll
    for (int idx = tid; idx < 200 * 32; idx += 256) {
        int widx = idx >> 5, c = idx & 31;
        int rw = (widx * 2341) >> 15; rw = rw > 13 ? 13 : rw;
        int cw = widx - rw * 14;
        int gi = wi0 + rw; gi = gi > 63 ? 63 : gi;
        int gj = wj0 + cw; gj = gj > 63 ? 63 : gj;
        Vs[widx][c] = f2tf32(qb[(size_t)(gi * 64 + gj) * 384 + 256 + c]);
    }

    // ---- softmax over dense rows (warp per 8 rows); store exp as tf32 ----
    {
        int p0 = warp * 8;
        #pragma unroll
        for (int pp = 0; pp < 8; pp++) {
            int p = p0 + pp;
            float v[7];
            float m = -1e30f;
            #pragma unroll
            for (int k = 0; k < 7; k++) {
                int col = lane + 32 * k;
                v[k] = (col < 200) ? __uint_as_float(P[p][col]) : -1e30f;
                m = fmaxf(m, v[k]);
            }
            #pragma unroll
            for (int o = 16; o > 0; o >>= 1) m = fmaxf(m, __shfl_xor_sync(0xffffffffu, m, o));
            float s = 0.f;
            #pragma unroll
            for (int k = 0; k < 7; k++) {
                int col = lane + 32 * k;
                float e = __expf(v[k] - m);
                s += e;
                if (col < 200) P[p][col] = f2tf32(e);
            }
            #pragma unroll
            for (int o = 16; o > 0; o >>= 1) s += __shfl_xor_sync(0xffffffffu, s, o);
            if (lane == 0) sinv[p] = 1.0f / s;
        }
    }
    __syncthreads();   // V + exp(P) + sinv ready

    // ---- AV MMA: O(64x32) = P(64x200) @ V(200x32); warp (mt rows, nh 16-col half) ----
    float oacc[2][4];
    #pragma unroll
    for (int nt = 0; nt < 2; nt++)
        #pragma unroll
        for (int i = 0; i < 4; i++) oacc[nt][i] = 0.f;

    int c0 = nh * 16;
    for (int kt = 0; kt < 200; kt += 8) {
        uint32_t af[4];
        int r = mt * 16 + grp;
        af[0] = P[r][kt + qk];     af[1] = P[r + 8][kt + qk];
        af[2] = P[r][kt + qk + 4]; af[3] = P[r + 8][kt + qk + 4];
        #pragma unroll
        for (int nt = 0; nt < 2; nt++) {
            uint32_t bf[2];
            bf[0] = Vs[kt + qk][c0 + nt * 8 + grp];
            bf[1] = Vs[kt + qk + 4][c0 + nt * 8 + grp];
            mma_tf32(oacc[nt], af, bf);
        }
    }

    // ---- epilogue: scale by 1/rowsum, write na ----
    {
        int r0 = mt * 16 + grp, r1 = r0 + 8;
        float inv0 = sinv[r0], inv1 = sinv[r1];
        int ia = i0 + (r0 >> 3), ja = j0 + (r0 & 7);
        int ib = i0 + (r1 >> 3), jb = j0 + (r1 & 7);
        size_t oa = (size_t)(n * HWP + ia * 64 + ja) * CDIM + h * DH;
        size_t ob = (size_t)(n * HWP + ib * 64 + jb) * CDIM + h * DH;
        #pragma unroll
        for (int nt = 0; nt < 2; nt++) {
            int cc0 = c0 + nt * 8 + 2 * qk;
            na[oa + cc0]     = oacc[nt][0] * inv0;
            na[oa + cc0 + 1] = oacc[nt][1] * inv0;
            na[ob + cc0]     = oacc[nt][2] * inv1;
            na[ob + cc0 + 1] = oacc[nt][3] * inv1;
        }
    }
}

// ---------------------------------------------------------------------------
// Fused proj GEMM + channel-attn gate + residual combine + LayerNorm2.
// ---------------------------------------------------------------------------
__global__ __launch_bounds__(128)
void k_proj_ln(const float* __restrict__ A /*na*/, const float* __restrict__ B /*proj_w*/,
               const float* __restrict__ bias,
               const float* __restrict__ xs, const float* __restrict__ t,
               const float* __restrict__ gsum,
               const float* __restrict__ ca1w, const float* __restrict__ ca1b,
               const float* __restrict__ ca2w, const float* __restrict__ ca2b,
               const float* __restrict__ w2, const float* __restrict__ b2,
               float* __restrict__ x2, float* __restrict__ xn2)
{
    __shared__ union SU {
        struct { uint32_t As[64][36]; uint32_t Bs[32][136]; } gm;
        float x2s[64][132];
    } sm;
    __shared__ float sgm[CDIM];
    __shared__ float sr7[7];
    __shared__ float sgarr[CDIM];

    int tid  = threadIdx.x;
    int lane = tid & 31;
    int warp = tid >> 5;
    int grp = lane >> 2, qk = lane & 3;
    int m0 = blockIdx.x * 64;
    int n = m0 >> 12;

    float acc[16][4];
    #pragma unroll
    for (int nt = 0; nt < 16; nt++)
        #pragma unroll
        for (int i = 0; i < 4; i++) acc[nt][i] = 0.f;

    int arow = tid >> 1, kseg = (tid & 1) * 16;
    int brow = tid >> 2, bcol = (tid & 3) * 32;

    for (int k0 = 0; k0 < 128; k0 += 32) {
        const float* ap = A + (size_t)(m0 + arow) * CDIM + k0 + kseg;
        #pragma unroll
        for (int i = 0; i < 4; i++) {
            float4 v = *(const float4*)(ap + i * 4);
            sm.gm.As[arow][kseg + i * 4 + 0] = f2tf32(v.x);
            sm.gm.As[arow][kseg + i * 4 + 1] = f2tf32(v.y);
            sm.gm.As[arow][kseg + i * 4 + 2] = f2tf32(v.z);
            sm.gm.As[arow][kseg + i * 4 + 3] = f2tf32(v.w);
        }
        const float* bp = B + (size_t)(k0 + brow) * CDIM + bcol;
        #pragma unroll
        for (int i = 0; i < 8; i++) {
            float4 v = *(const float4*)(bp + i * 4);
            sm.gm.Bs[brow][bcol + i * 4 + 0] = f2tf32(v.x);
            sm.gm.Bs[brow][bcol + i * 4 + 1] = f2tf32(v.y);
            sm.gm.Bs[brow][bcol + i * 4 + 2] = f2tf32(v.z);
            sm.gm.Bs[brow][bcol + i * 4 + 3] = f2tf32(v.w);
        }
        __syncthreads();
        #pragma unroll
        for (int kk = 0; kk < 32; kk += 8) {
            uint32_t af[4];
            int r = warp * 16 + grp;
            af[0] = sm.gm.As[r][kk + qk];     af[1] = sm.gm.As[r + 8][kk + qk];
            af[2] = sm.gm.As[r][kk + qk + 4]; af[3] = sm.gm.As[r + 8][kk + qk + 4];
            #pragma unroll
            for (int nt = 0; nt < 16; nt++) {
                uint32_t bf[2];
                bf[0] = sm.gm.Bs[kk + qk][nt * 8 + grp];
                bf[1] = sm.gm.Bs[kk + qk + 4][nt * 8 + grp];
                mma_tf32(acc[nt], af, bf);
            }
        }
        __syncthreads();
    }

    // ---- channel-attention gate in-block ----
    sgm[tid] = gsum[n * CDIM + tid] * (1.0f / HWP);
    __syncthreads();
    if (warp == 0) {
        float part[7];
        #pragma unroll
        for (int j = 0; j < 7; j++) part[j] = 0.f;
        #pragma unroll
        for (int k = 0; k < 4; k++) {
            int c = lane + 32 * k;
            float gv = sgm[c];
            #pragma unroll
            for (int j = 0; j < 7; j++) part[j] += gv * ca1w[c * 7 + j];
        }
        #pragma unroll
        for (int j = 0; j < 7; j++) {
            #pragma unroll
            for (int o = 16; o > 0; o >>= 1)
                part[j] += __shfl_xor_sync(0xffffffffu, part[j], o);
        }
        if (lane == 0) {
            #pragma unroll
            for (int j = 0; j < 7; j++) sr7[j] = fmaxf(part[j] + ca1b[j], 0.f);
        }
    }
    __syncthreads();
    {
        float s = ca2b[tid];
        #pragma unroll
        for (int j = 0; j < 7; j++) s += sr7[j] * ca2w[j * CDIM + tid];
        sgarr[tid] = (1.0f / (1.0f + expf(-s))) * 0.02f;
    }
    __syncthreads();

    {
        int r = warp * 16 + grp;
        size_t ro0 = (size_t)(m0 + r) * CDIM;
        size_t ro1 = (size_t)(m0 + r + 8) * CDIM;
        #pragma unroll
        for (int nt = 0; nt < 16; nt++) {
            int c = nt * 8 + 2 * qk;
            float bb0 = bias[c], bb1 = bias[c + 1];
            float g0 = sgarr[c], g1 = sgarr[c + 1];
            sm.x2s[r][c]         = acc[nt][0] + bb0 + xs[ro0 + c]     + t[ro0 + c]     * g0;
            sm.x2s[r][c + 1]     = acc[nt][1] + bb1 + xs[ro0 + c + 1] + t[ro0 + c + 1] * g1;
            sm.x2s[r + 8][c]     = acc[nt][2] + bb0 + xs[ro1 + c]     + t[ro1 + c]     * g0;
            sm.x2s[r + 8][c + 1] = acc[nt][3] + bb1 + xs[ro1 + c + 1] + t[ro1 + c + 1] * g1;
        }
    }
    __syncthreads();

    float w2r[4], b2r[4];
    #pragma unroll
    for (int k = 0; k < 4; k++) { w2r[k] = w2[lane + 32 * k]; b2r[k] = b2[lane + 32 * k]; }

    #pragma unroll
    for (int rr = 0; rr < 16; rr++) {
        int r = warp * 16 + rr;
        float v[4];
        float sum = 0.f, sq = 0.f;
        #pragma unroll
        for (int k = 0; k < 4; k++) {
            v[k] = sm.x2s[r][lane + 32 * k];
            sum += v[k]; sq += v[k] * v[k];
        }
        #pragma unroll
        for (int o = 16; o > 0; o >>= 1) {
            sum += __shfl_xor_sync(0xffffffffu, sum, o);
            sq  += __shfl_xor_sync(0xffffffffu, sq, o);
        }
        float mu = sum * (1.0f / CDIM);
        float rs = rsqrtf(sq * (1.0f / CDIM) - mu * mu + 1e-5f);
        size_t ro = (size_t)(m0 + r) * CDIM;
        #pragma unroll
        for (int k = 0; k < 4; k++) {
            x2[ro + lane + 32 * k]  = v[k];
            xn2[ro + lane + 32 * k] = (v[k] - mu) * rs * w2r[k] + b2r[k];
        }
    }
}

// ---------------------------------------------------------------------------
// Launch
// ---------------------------------------------------------------------------
extern "C" void kernel_launch(void* const* d_in, const int* in_sizes, int n_in,
                              void* d_out, int out_size)
{
    const float* x      = (const float*)d_in[0];
    const float* ln1_w  = (const float*)d_in[1];
    const float* ln1_b  = (const float*)d_in[2];
    const float* ln2_w  = (const float*)d_in[3];
    const float* ln2_b  = (const float*)d_in[4];
    const float* qkv_w  = (const float*)d_in[5];
    const float* qkv_b  = (const float*)d_in[6];
    const float* proj_w = (const float*)d_in[7];
    const float* proj_b = (const float*)d_in[8];
    const float* rpb    = (const float*)d_in[9];
    const float* conv1_w= (const float*)d_in[10];
    const float* conv1_b= (const float*)d_in[11];
    const float* conv2_w= (const float*)d_in[12];
    const float* conv2_b= (const float*)d_in[13];
    const float* ca1_w  = (const float*)d_in[14];
    const float* ca1_b  = (const float*)d_in[15];
    const float* ca2_w  = (const float*)d_in[16];
    const float* ca2_b  = (const float*)d_in[17];
    const float* fc1_w  = (const float*)d_in[18];
    const float* fc1_b  = (const float*)d_in[19];
    const float* fc2_w  = (const float*)d_in[20];
    const float* fc2_b  = (const float*)d_in[21];
    float* out = (float*)d_out;

    float* scr = nullptr;
    cudaGetSymbolAddress((void**)&scr, d_scratch);
    float* xs   = scr + OFF_XS;
    float* xn   = scr + OFF_XN;
    float* qkv  = scr + OFF_QKV;
    float* t    = scr + OFF_T;
    float* na   = scr + OFF_NA;
    float* x2   = scr + OFF_X2;
    float* xn2  = scr + OFF_XN2;
    float* h1   = scr + OFF_H1;
    float* gsum = scr + OFF_GSUM;

    cudaFuncSetAttribute(k_na, cudaFuncAttributeMaxDynamicSharedMemorySize, NA_SMEM);

    // 1. transpose + LN1 (+ zero gsum)
    k_transpose_ln<<<ROWS / 32, 128>>>(x, ln1_w, ln1_b, xs, xn, gsum);
    // 2. qkv GEMM: 16384 x 384 x 128
    k_mma<EPI_NONE><<<dim3(6, ROWS / 64), 128>>>(xn, qkv_w, qkv_b, qkv,
                                                 ROWS, 384, 128, nullptr);
    // 3. fused conv1+gelu+conv2+colsum
    k_conv<<<ROWS / 64, 128>>>(xn, conv1_w, conv1_b, conv2_w, conv2_b, t, gsum);
    // 4. neighborhood attention (full tensor-core)
    k_na<<<dim3(64, NB * NHEAD), 256, NA_SMEM>>>(qkv, rpb, na);
    // 5. fused proj + gate + residual + LN2
    k_proj_ln<<<ROWS / 64, 128>>>(na, proj_w, proj_b, xs, t, gsum,
                                  ca1_w, ca1_b, ca2_w, ca2_b,
                                  ln2_w, ln2_b, x2, xn2);
    // 6. fc1 + gelu: 16384 x 512 x 128
    k_mma<EPI_GELU><<<dim3(8, ROWS / 64), 128>>>(xn2, fc1_w, fc1_b, h1,
                                                 ROWS, 512, 128, nullptr);
    // 7. fc2 + residual, write NCHW output
    k_mma<EPI_OUT><<<dim3(2, ROWS / 64), 128>>>(h1, fc2_w, fc2_b, out,
                                                ROWS, 128, 512, x2);
}